// round 2
// baseline (speedup 1.0000x reference)
#include <cuda_runtime.h>
#include <math.h>

// Problem dims (fixed by the reference)
#define Bc  4
#define Sc  2048
#define Ec  768
#define Dc  768
#define Hc  12
#define DHc 64
#define Fc  3072

#define BM 64
#define BN 64
#define BK 16
#define NT_THREADS 256

// ---------------- scratch (device globals: allocation-free) ----------------
__device__ float g_q [(size_t)Bc*Hc*Sc*DHc];   // [B,H,S,dh]
__device__ float g_k [(size_t)Bc*Hc*Sc*DHc];   // [B,H,S,dh]
__device__ float g_vt[(size_t)Bc*Hc*DHc*Sc];   // [B,H,dh,S]  (transposed V)
__device__ float g_sc[(size_t)Bc*Hc*Sc*Sc];    // [B,H,S,S] scores/attn (805 MB)
__device__ float g_a [(size_t)Bc*Sc*Dc];       // concat-heads / post-LN1
__device__ float g_h [(size_t)Bc*Sc*Fc];       // FFN hidden
__device__ float g_b [(size_t)Bc*Sc*Dc];       // FFN out pre-LN2

struct EpiParams {
    float* out;
    const float* bias;
    const int* mask;          // jax bool coerced to int32 by the harness
    float scale;
};

// ---------------------------------------------------------------------------
// Generic NT GEMM: C[M,N] = A[M,K] @ B[N,K]^T, batched via blockIdx.z.
// MODE epilogues:
//   0: out[m*N+n] = acc + bias[n]
//   1: out[m*N+n] = relu(acc + bias[n])
//   2: QK scatter:  m=(b,s), n=(h,d) -> out[b,h,s,d] = acc + bias[n]
//   3: Vt scatter:  m=(b,s), n=(h,d) -> out[b,h,d,s] = acc + bias[n]
//   4: scores: val = acc*scale; mask[b,m,n] -> -1000; out[z,m,n]
//   5: attn@V -> concat heads: out[b, m, h*dh + n] = acc   (z=(b,h))
// ---------------------------------------------------------------------------
template<int MODE>
__global__ void __launch_bounds__(NT_THREADS)
gemm_nt(const float* __restrict__ A, const float* __restrict__ Bm,
        int M, int N, int K, long strideA, long strideB, EpiParams p)
{
    const int z = blockIdx.z;
    A  += (long)z * strideA;
    Bm += (long)z * strideB;

    __shared__ float As[BK][BM];
    __shared__ float Bs[BK][BN];

    const int tid = threadIdx.x;
    const int tx  = tid & 15;       // 0..15 -> N
    const int ty  = tid >> 4;       // 0..15 -> M
    const int m0  = blockIdx.y * BM;
    const int n0  = blockIdx.x * BN;

    float acc[4][4];
    #pragma unroll
    for (int i = 0; i < 4; ++i)
        #pragma unroll
        for (int j = 0; j < 4; ++j) acc[i][j] = 0.f;

    const int lr = tid >> 2;        // 0..63 row within tile
    const int lc = (tid & 3) * 4;   // 0,4,8,12

    for (int k0 = 0; k0 < K; k0 += BK) {
        float4 va = *reinterpret_cast<const float4*>(&A [(long)(m0 + lr) * K + k0 + lc]);
        float4 vb = *reinterpret_cast<const float4*>(&Bm[(long)(n0 + lr) * K + k0 + lc]);
        As[lc+0][lr] = va.x; As[lc+1][lr] = va.y; As[lc+2][lr] = va.z; As[lc+3][lr] = va.w;
        Bs[lc+0][lr] = vb.x; Bs[lc+1][lr] = vb.y; Bs[lc+2][lr] = vb.z; Bs[lc+3][lr] = vb.w;
        __syncthreads();

        #pragma unroll
        for (int k = 0; k < BK; ++k) {
            float ra[4], rb[4];
            #pragma unroll
            for (int i = 0; i < 4; ++i) ra[i] = As[k][ty * 4 + i];
            #pragma unroll
            for (int j = 0; j < 4; ++j) rb[j] = Bs[k][tx * 4 + j];
            #pragma unroll
            for (int i = 0; i < 4; ++i)
                #pragma unroll
                for (int j = 0; j < 4; ++j) acc[i][j] = fmaf(ra[i], rb[j], acc[i][j]);
        }
        __syncthreads();
    }

    #pragma unroll
    for (int i = 0; i < 4; ++i) {
        const int m = m0 + ty * 4 + i;
        #pragma unroll
        for (int j = 0; j < 4; ++j) {
            const int n = n0 + tx * 4 + j;
            float v = acc[i][j];
            if (MODE == 0) {
                p.out[(long)m * N + n] = v + p.bias[n];
            } else if (MODE == 1) {
                v += p.bias[n];
                p.out[(long)m * N + n] = v > 0.f ? v : 0.f;
            } else if (MODE == 2) {
                const int b = m / Sc, s = m % Sc;
                const int h = n / DHc, d = n % DHc;
                p.out[(((long)b * Hc + h) * Sc + s) * DHc + d] = v + p.bias[n];
            } else if (MODE == 3) {
                const int b = m / Sc, s = m % Sc;
                const int h = n / DHc, d = n % DHc;
                p.out[(((long)b * Hc + h) * DHc + d) * Sc + s] = v + p.bias[n];
            } else if (MODE == 4) {
                const int b = z / Hc;
                float val = v * p.scale;
                if (p.mask[((long)b * Sc + m) * Sc + n] != 0) val = -1000.f;
                p.out[((long)z * Sc + m) * Sc + n] = val;
            } else if (MODE == 5) {
                const int b = z / Hc, h = z % Hc;
                p.out[((long)b * Sc + m) * Dc + h * DHc + n] = v;
            }
        }
    }
}

// ---------------------------------------------------------------------------
// Softmax over the QUERY axis (axis s of scores[b,h,s,t]).
// One thread per column t; rows iterated -> fully coalesced (stride S across s).
// ---------------------------------------------------------------------------
__global__ void softmax_query_kernel(float* __restrict__ sc)
{
    const int t = blockIdx.x * blockDim.x + threadIdx.x;
    const size_t base = (size_t)blockIdx.y * Sc * Sc;

    float m = -3.4e38f, sum = 0.f;
    for (int s = 0; s < Sc; ++s) {
        float x = sc[base + (size_t)s * Sc + t];
        if (x > m) { sum = sum * __expf(m - x) + 1.f; m = x; }
        else       { sum += __expf(x - m); }
    }
    const float inv = 1.f / sum;
    for (int s = 0; s < Sc; ++s) {
        const size_t idx = base + (size_t)s * Sc + t;
        sc[idx] = __expf(sc[idx] - m) * inv;
    }
}

// ---------------------------------------------------------------------------
// out = LayerNorm(in)*gamma + beta + in  (row = 768, block = 256 threads)
// ---------------------------------------------------------------------------
__global__ void ln_residual_kernel(const float* __restrict__ in,
                                   const float* __restrict__ gamma,
                                   const float* __restrict__ beta,
                                   float* __restrict__ out)
{
    const size_t row = blockIdx.x;
    const float* xr = in + row * Dc;
    const int tid = threadIdx.x;

    const float v0 = xr[tid], v1 = xr[tid + 256], v2 = xr[tid + 512];

    __shared__ float red[256];
    red[tid] = v0 + v1 + v2;
    __syncthreads();
    #pragma unroll
    for (int o = 128; o > 0; o >>= 1) {
        if (tid < o) red[tid] += red[tid + o];
        __syncthreads();
    }
    const float mu = red[0] * (1.f / Dc);
    __syncthreads();

    const float d0 = v0 - mu, d1 = v1 - mu, d2 = v2 - mu;
    red[tid] = d0 * d0 + d1 * d1 + d2 * d2;
    __syncthreads();
    #pragma unroll
    for (int o = 128; o > 0; o >>= 1) {
        if (tid < o) red[tid] += red[tid + o];
        __syncthreads();
    }
    const float rstd = rsqrtf(red[0] * (1.f / Dc) + 1e-5f);

    float* orow = out + row * Dc;
    orow[tid]       = d0 * rstd * gamma[tid]       + beta[tid]       + v0;
    orow[tid + 256] = d1 * rstd * gamma[tid + 256] + beta[tid + 256] + v1;
    orow[tid + 512] = d2 * rstd * gamma[tid + 512] + beta[tid + 512] + v2;
}

// ---------------------------------------------------------------------------
extern "C" void kernel_launch(void* const* d_in, const int* in_sizes, int n_in,
                              void* d_out, int out_size)
{
    (void)in_sizes; (void)n_in; (void)out_size;
    const float* x    = (const float*)d_in[0];
    const int*   mask = (const int*)d_in[1];      // bool -> int32 per harness dtypes
    const float* Wq = (const float*)d_in[2];
    const float* bq = (const float*)d_in[3];
    const float* Wk = (const float*)d_in[4];
    const float* bk = (const float*)d_in[5];
    const float* Wv = (const float*)d_in[6];
    const float* bv = (const float*)d_in[7];
    const float* gamma = (const float*)d_in[8];
    const float* beta  = (const float*)d_in[9];
    const float* W1 = (const float*)d_in[10];
    const float* b1 = (const float*)d_in[11];
    const float* W2 = (const float*)d_in[12];
    const float* b2 = (const float*)d_in[13];
    float* out = (float*)d_out;

    float *q, *k, *vt, *sc, *a, *h, *bb;
    cudaGetSymbolAddress((void**)&q,  g_q);
    cudaGetSymbolAddress((void**)&k,  g_k);
    cudaGetSymbolAddress((void**)&vt, g_vt);
    cudaGetSymbolAddress((void**)&sc, g_sc);
    cudaGetSymbolAddress((void**)&a,  g_a);
    cudaGetSymbolAddress((void**)&h,  g_h);
    cudaGetSymbolAddress((void**)&bb, g_b);

    const dim3 blk(NT_THREADS);
    const int MS = Bc * Sc;               // 8192 rows
    const float scale = 1.0f / sqrtf((float)Sc);

    // 1) QKV projections: [8192,768] @ [768,768]^T, scattered per head.
    {
        dim3 grid(Dc / BN, MS / BM, 1);
        EpiParams pq{q,  bq, nullptr, 0.f};
        EpiParams pk{k,  bk, nullptr, 0.f};
        EpiParams pv{vt, bv, nullptr, 0.f};
        gemm_nt<2><<<grid, blk>>>(x, Wq, MS, Dc, Ec, 0, 0, pq);
        gemm_nt<2><<<grid, blk>>>(x, Wk, MS, Dc, Ec, 0, 0, pk);
        gemm_nt<3><<<grid, blk>>>(x, Wv, MS, Dc, Ec, 0, 0, pv);
    }

    // 2) scores = q @ k^T / sqrt(S), mask -> -1000   (batched over B*H)
    {
        dim3 grid(Sc / BN, Sc / BM, Bc * Hc);
        EpiParams ps{sc, nullptr, mask, scale};
        gemm_nt<4><<<grid, blk>>>(q, k, Sc, Sc, DHc,
                                  (long)Sc * DHc, (long)Sc * DHc, ps);
    }

    // 3) softmax over the QUERY axis (column-wise)
    {
        dim3 grid(Sc / 256, Bc * Hc);
        softmax_query_kernel<<<grid, 256>>>(sc);
    }

    // 4) o = attn @ v  -> concat heads into a[b,s,D]
    {
        dim3 grid(DHc / BN, Sc / BM, Bc * Hc);
        EpiParams po{a, nullptr, nullptr, 0.f};
        gemm_nt<5><<<grid, blk>>>(sc, vt, Sc, DHc, Sc,
                                  (long)Sc * Sc, (long)DHc * Sc, po);
    }

    // 5) a = LN(a) + a
    ln_residual_kernel<<<MS, 256>>>(a, gamma, beta, a);

    // 6) h = relu(a @ W1^T + b1)
    {
        dim3 grid(Fc / BN, MS / BM, 1);
        EpiParams p1{h, b1, nullptr, 0.f};
        gemm_nt<1><<<grid, blk>>>(a, W1, MS, Fc, Dc, 0, 0, p1);
    }

    // 7) bb = h @ W2^T + b2
    {
        dim3 grid(Dc / BN, MS / BM, 1);
        EpiParams p2{bb, b2, nullptr, 0.f};
        gemm_nt<0><<<grid, blk>>>(h, W2, MS, Dc, Fc, 0, 0, p2);
    }

    // 8) out = LN(bb) + bb
    ln_residual_kernel<<<MS, 256>>>(bb, gamma, beta, out);
}

// round 4
// speedup vs baseline: 1.3115x; 1.3115x over previous
#include <cuda_runtime.h>
#include <math.h>

// Problem dims (fixed by the reference)
#define Bc  4
#define Sc  2048
#define Ec  768
#define Dc  768
#define Hc  12
#define DHc 64
#define Fc  3072

#define BK 16

// ---------------- scratch (device globals: allocation-free) ----------------
__device__ float g_q [(size_t)Bc*Hc*Sc*DHc];   // [B,H,S,dh]
__device__ float g_k [(size_t)Bc*Hc*Sc*DHc];   // [B,H,S,dh]
__device__ float g_vt[(size_t)Bc*Hc*DHc*Sc];   // [B,H,dh,S]  (transposed V)
__device__ float g_sc[(size_t)Bc*Hc*Sc*Sc];    // [B,H,S,S] raw masked scores (805 MB)
__device__ float g_m [(size_t)Bc*Hc*Sc];       // per-column max
__device__ float g_iz[(size_t)Bc*Hc*Sc];       // per-column 1/sum(exp)
__device__ float g_a [(size_t)Bc*Sc*Dc];       // concat-heads / post-LN1
__device__ float g_h [(size_t)Bc*Sc*Fc];       // FFN hidden
__device__ float g_b [(size_t)Bc*Sc*Dc];       // FFN out pre-LN2

struct EpiParams {
    float* out;
    const float* bias;
    const int* mask;          // jax bool coerced to int32 by the harness
    float scale;
};

// ---------------------------------------------------------------------------
// SGEMM NT: C[M,N] = A[M,K] @ B[N,K]^T, batched via blockIdx.z.
// BM=128 fixed, BN_/TN templated. 256 threads, TM=8 rows per thread.
// MODE epilogues:
//   0: out[m*N+n] = acc + bias[n]
//   1: out[m*N+n] = relu(acc + bias[n])
//   2: QK scatter:  m=(b,s), n=(h,d) -> out[b,h,s,d] = acc + bias[n]
//   3: Vt scatter:  m=(b,s), n=(h,d) -> out[b,h,d,s] = acc + bias[n]
//   4: scores: val = acc*scale; mask[b,m,n] -> -1000; out[z,m,n]
// ---------------------------------------------------------------------------
template<int BN_, int TN, int MODE>
__global__ void __launch_bounds__(256)
gemm_nt(const float* __restrict__ A, const float* __restrict__ Bm,
        int M, int N, int K, long strideA, long strideB, EpiParams p)
{
    const int z = blockIdx.z;
    A  += (long)z * strideA;
    Bm += (long)z * strideB;

    __shared__ float As[2][BK][128];
    __shared__ float Bs[2][BK][BN_];

    const int tid = threadIdx.x;
    const int tx  = tid & 15;          // 0..15 -> N groups of TN
    const int ty  = tid >> 4;          // 0..15 -> M groups of 8
    const int m0  = blockIdx.y * 128;
    const int n0  = blockIdx.x * BN_;

    const int lr = tid >> 2;           // 0..63
    const int lc = (tid & 3) * 4;      // 0,4,8,12

    float acc[8][TN];
    #pragma unroll
    for (int i = 0; i < 8; ++i)
        #pragma unroll
        for (int j = 0; j < TN; ++j) acc[i][j] = 0.f;

    const int nk = K / BK;

    // ---- load tile 0 ----
    {
        float4 a0 = *reinterpret_cast<const float4*>(&A [(long)(m0 + lr)      * K + lc]);
        float4 a1 = *reinterpret_cast<const float4*>(&A [(long)(m0 + lr + 64) * K + lc]);
        As[0][lc+0][lr] = a0.x; As[0][lc+1][lr] = a0.y; As[0][lc+2][lr] = a0.z; As[0][lc+3][lr] = a0.w;
        As[0][lc+0][lr+64] = a1.x; As[0][lc+1][lr+64] = a1.y; As[0][lc+2][lr+64] = a1.z; As[0][lc+3][lr+64] = a1.w;
        float4 b0 = *reinterpret_cast<const float4*>(&Bm[(long)(n0 + lr) * K + lc]);
        Bs[0][lc+0][lr] = b0.x; Bs[0][lc+1][lr] = b0.y; Bs[0][lc+2][lr] = b0.z; Bs[0][lc+3][lr] = b0.w;
        if (BN_ == 128) {
            float4 b1 = *reinterpret_cast<const float4*>(&Bm[(long)(n0 + lr + 64) * K + lc]);
            Bs[0][lc+0][lr+64] = b1.x; Bs[0][lc+1][lr+64] = b1.y; Bs[0][lc+2][lr+64] = b1.z; Bs[0][lc+3][lr+64] = b1.w;
        }
    }
    __syncthreads();

    for (int kt = 0; kt < nk; ++kt) {
        const int cur = kt & 1, nxt = cur ^ 1;
        float4 pa0, pa1, pb0, pb1;
        const bool has_next = (kt + 1 < nk);
        if (has_next) {
            const int k0 = (kt + 1) * BK;
            pa0 = *reinterpret_cast<const float4*>(&A [(long)(m0 + lr)      * K + k0 + lc]);
            pa1 = *reinterpret_cast<const float4*>(&A [(long)(m0 + lr + 64) * K + k0 + lc]);
            pb0 = *reinterpret_cast<const float4*>(&Bm[(long)(n0 + lr) * K + k0 + lc]);
            if (BN_ == 128)
                pb1 = *reinterpret_cast<const float4*>(&Bm[(long)(n0 + lr + 64) * K + k0 + lc]);
        }

        #pragma unroll
        for (int k = 0; k < BK; ++k) {
            float ra[8], rb[TN];
            const float4* a4 = reinterpret_cast<const float4*>(&As[cur][k][ty * 8]);
            float4 av0 = a4[0], av1 = a4[1];
            ra[0]=av0.x; ra[1]=av0.y; ra[2]=av0.z; ra[3]=av0.w;
            ra[4]=av1.x; ra[5]=av1.y; ra[6]=av1.z; ra[7]=av1.w;
            const float4* b4 = reinterpret_cast<const float4*>(&Bs[cur][k][tx * TN]);
            float4 bv0 = b4[0];
            rb[0]=bv0.x; rb[1]=bv0.y; rb[2]=bv0.z; rb[3]=bv0.w;
            if (TN == 8) {
                float4 bv1 = b4[1];
                rb[4]=bv1.x; rb[5]=bv1.y; rb[6]=bv1.z; rb[7]=bv1.w;
            }
            #pragma unroll
            for (int i = 0; i < 8; ++i)
                #pragma unroll
                for (int j = 0; j < TN; ++j) acc[i][j] = fmaf(ra[i], rb[j], acc[i][j]);
        }

        if (has_next) {
            As[nxt][lc+0][lr] = pa0.x; As[nxt][lc+1][lr] = pa0.y; As[nxt][lc+2][lr] = pa0.z; As[nxt][lc+3][lr] = pa0.w;
            As[nxt][lc+0][lr+64] = pa1.x; As[nxt][lc+1][lr+64] = pa1.y; As[nxt][lc+2][lr+64] = pa1.z; As[nxt][lc+3][lr+64] = pa1.w;
            Bs[nxt][lc+0][lr] = pb0.x; Bs[nxt][lc+1][lr] = pb0.y; Bs[nxt][lc+2][lr] = pb0.z; Bs[nxt][lc+3][lr] = pb0.w;
            if (BN_ == 128) {
                Bs[nxt][lc+0][lr+64] = pb1.x; Bs[nxt][lc+1][lr+64] = pb1.y; Bs[nxt][lc+2][lr+64] = pb1.z; Bs[nxt][lc+3][lr+64] = pb1.w;
            }
            __syncthreads();
        }
    }

    // ---- epilogue ----
    #pragma unroll
    for (int i = 0; i < 8; ++i) {
        const int m = m0 + ty * 8 + i;
        #pragma unroll
        for (int j = 0; j < TN; j += 4) {
            const int n = n0 + tx * TN + j;
            float4 v = make_float4(acc[i][j], acc[i][j+1], acc[i][j+2], acc[i][j+3]);
            if (MODE == 0) {
                const float4 bi = *reinterpret_cast<const float4*>(&p.bias[n]);
                v.x += bi.x; v.y += bi.y; v.z += bi.z; v.w += bi.w;
                *reinterpret_cast<float4*>(&p.out[(long)m * N + n]) = v;
            } else if (MODE == 1) {
                const float4 bi = *reinterpret_cast<const float4*>(&p.bias[n]);
                v.x = fmaxf(v.x + bi.x, 0.f); v.y = fmaxf(v.y + bi.y, 0.f);
                v.z = fmaxf(v.z + bi.z, 0.f); v.w = fmaxf(v.w + bi.w, 0.f);
                *reinterpret_cast<float4*>(&p.out[(long)m * N + n]) = v;
            } else if (MODE == 2) {
                const int b = m / Sc, s = m % Sc;
                const int h = n / DHc, d = n % DHc;
                const float4 bi = *reinterpret_cast<const float4*>(&p.bias[n]);
                v.x += bi.x; v.y += bi.y; v.z += bi.z; v.w += bi.w;
                *reinterpret_cast<float4*>(&p.out[(((long)b * Hc + h) * Sc + s) * DHc + d]) = v;
            } else if (MODE == 3) {
                const int b = m / Sc, s = m % Sc;
                const int h = n / DHc, d = n % DHc;
                float* o = &p.out[(((long)b * Hc + h) * DHc + d) * Sc + s];
                o[0]          = v.x + p.bias[n];
                o[(long)Sc]   = v.y + p.bias[n+1];
                o[(long)Sc*2] = v.z + p.bias[n+2];
                o[(long)Sc*3] = v.w + p.bias[n+3];
            } else if (MODE == 4) {
                const int b = z / Hc;
                const int4 mk = *reinterpret_cast<const int4*>(&p.mask[((long)b * Sc + m) * Sc + n]);
                v.x = mk.x ? -1000.f : v.x * p.scale;
                v.y = mk.y ? -1000.f : v.y * p.scale;
                v.z = mk.z ? -1000.f : v.z * p.scale;
                v.w = mk.w ? -1000.f : v.w * p.scale;
                *reinterpret_cast<float4*>(&p.out[((long)z * Sc + m) * Sc + n]) = v;
            }
        }
    }
}

// ---------------------------------------------------------------------------
// attn@V with on-the-fly softmax normalization:
//   A tile element (s,t) -> exp(sc[s,t] - m[t]) * iz[t]
// C[b, s, h*64+n] = sum_t p(s,t) * vt[d=n, t].  BM=128, BN=64, TN=4.
// z = b*H + h.
// ---------------------------------------------------------------------------
__global__ void __launch_bounds__(256)
gemm_av(const float* __restrict__ SC, const float* __restrict__ VT,
        const float* __restrict__ Mx, const float* __restrict__ IZ,
        float* __restrict__ out)
{
    const int z = blockIdx.z;
    const float* A  = SC + (long)z * Sc * Sc;       // [S, S]
    const float* Bm = VT + (long)z * DHc * Sc;      // [64, S]
    const float* mz = Mx + (long)z * Sc;
    const float* iz = IZ + (long)z * Sc;

    __shared__ float As[2][BK][128];
    __shared__ float Bs[2][BK][64];

    const int tid = threadIdx.x;
    const int tx  = tid & 15;
    const int ty  = tid >> 4;
    const int m0  = blockIdx.y * 128;

    const int lr = tid >> 2;
    const int lc = (tid & 3) * 4;

    float acc[8][4];
    #pragma unroll
    for (int i = 0; i < 8; ++i)
        #pragma unroll
        for (int j = 0; j < 4; ++j) acc[i][j] = 0.f;

    const int nk = Sc / BK;   // 128

    auto loadA = [&](int k0, float4& o0, float4& o1) {
        const float4 mv = *reinterpret_cast<const float4*>(&mz[k0 + lc]);
        const float4 zv = *reinterpret_cast<const float4*>(&iz[k0 + lc]);
        float4 a0 = *reinterpret_cast<const float4*>(&A[(long)(m0 + lr)      * Sc + k0 + lc]);
        float4 a1 = *reinterpret_cast<const float4*>(&A[(long)(m0 + lr + 64) * Sc + k0 + lc]);
        o0.x = __expf(a0.x - mv.x) * zv.x; o0.y = __expf(a0.y - mv.y) * zv.y;
        o0.z = __expf(a0.z - mv.z) * zv.z; o0.w = __expf(a0.w - mv.w) * zv.w;
        o1.x = __expf(a1.x - mv.x) * zv.x; o1.y = __expf(a1.y - mv.y) * zv.y;
        o1.z = __expf(a1.z - mv.z) * zv.z; o1.w = __expf(a1.w - mv.w) * zv.w;
    };

    // tile 0
    {
        float4 a0, a1;
        loadA(0, a0, a1);
        As[0][lc+0][lr] = a0.x; As[0][lc+1][lr] = a0.y; As[0][lc+2][lr] = a0.z; As[0][lc+3][lr] = a0.w;
        As[0][lc+0][lr+64] = a1.x; As[0][lc+1][lr+64] = a1.y; As[0][lc+2][lr+64] = a1.z; As[0][lc+3][lr+64] = a1.w;
        float4 b0 = *reinterpret_cast<const float4*>(&Bm[(long)lr * Sc + lc]);
        Bs[0][lc+0][lr] = b0.x; Bs[0][lc+1][lr] = b0.y; Bs[0][lc+2][lr] = b0.z; Bs[0][lc+3][lr] = b0.w;
    }
    __syncthreads();

    for (int kt = 0; kt < nk; ++kt) {
        const int cur = kt & 1, nxt = cur ^ 1;
        float4 pa0, pa1, pb0;
        const bool has_next = (kt + 1 < nk);
        if (has_next) {
            const int k0 = (kt + 1) * BK;
            loadA(k0, pa0, pa1);
            pb0 = *reinterpret_cast<const float4*>(&Bm[(long)lr * Sc + k0 + lc]);
        }

        #pragma unroll
        for (int k = 0; k < BK; ++k) {
            float ra[8], rb[4];
            const float4* a4 = reinterpret_cast<const float4*>(&As[cur][k][ty * 8]);
            float4 av0 = a4[0], av1 = a4[1];
            ra[0]=av0.x; ra[1]=av0.y; ra[2]=av0.z; ra[3]=av0.w;
            ra[4]=av1.x; ra[5]=av1.y; ra[6]=av1.z; ra[7]=av1.w;
            const float4 bv = reinterpret_cast<const float4*>(&Bs[cur][k][tx * 4])[0];
            rb[0]=bv.x; rb[1]=bv.y; rb[2]=bv.z; rb[3]=bv.w;
            #pragma unroll
            for (int i = 0; i < 8; ++i)
                #pragma unroll
                for (int j = 0; j < 4; ++j) acc[i][j] = fmaf(ra[i], rb[j], acc[i][j]);
        }

        if (has_next) {
            As[nxt][lc+0][lr] = pa0.x; As[nxt][lc+1][lr] = pa0.y; As[nxt][lc+2][lr] = pa0.z; As[nxt][lc+3][lr] = pa0.w;
            As[nxt][lc+0][lr+64] = pa1.x; As[nxt][lc+1][lr+64] = pa1.y; As[nxt][lc+2][lr+64] = pa1.z; As[nxt][lc+3][lr+64] = pa1.w;
            Bs[nxt][lc+0][lr] = pb0.x; Bs[nxt][lc+1][lr] = pb0.y; Bs[nxt][lc+2][lr] = pb0.z; Bs[nxt][lc+3][lr] = pb0.w;
            __syncthreads();
        }
    }

    const int b = z / Hc, h = z % Hc;
    #pragma unroll
    for (int i = 0; i < 8; ++i) {
        const int s = m0 + ty * 8 + i;
        const int d = tx * 4;
        float4 v = make_float4(acc[i][0], acc[i][1], acc[i][2], acc[i][3]);
        *reinterpret_cast<float4*>(&out[((long)b * Sc + s) * Dc + h * DHc + d]) = v;
    }
}

// ---------------------------------------------------------------------------
// Column-softmax stats: per column t of scores[z,s,t], compute max m_t and
// iz_t = 1/sum_s exp(sc - m_t).  Coalesced: thread per column.
// ---------------------------------------------------------------------------
__global__ void softmax_stats_kernel(const float* __restrict__ sc,
                                     float* __restrict__ Mx, float* __restrict__ IZ)
{
    const int t = blockIdx.x * blockDim.x + threadIdx.x;
    const int z = blockIdx.y;
    const size_t base = (size_t)z * Sc * Sc;

    float m = -3.4e38f, sum = 0.f;
    for (int s = 0; s < Sc; ++s) {
        float x = sc[base + (size_t)s * Sc + t];
        if (x > m) { sum = sum * __expf(m - x) + 1.f; m = x; }
        else       { sum += __expf(x - m); }
    }
    Mx[(size_t)z * Sc + t] = m;
    IZ[(size_t)z * Sc + t] = 1.f / sum;
}

// ---------------------------------------------------------------------------
// out = LayerNorm(in)*gamma + beta + in  (row = 768, block = 256 threads)
// ---------------------------------------------------------------------------
__global__ void ln_residual_kernel(const float* __restrict__ in,
                                   const float* __restrict__ gamma,
                                   const float* __restrict__ beta,
                                   float* __restrict__ out)
{
    const size_t row = blockIdx.x;
    const float* xr = in + row * Dc;
    const int tid = threadIdx.x;

    const float v0 = xr[tid], v1 = xr[tid + 256], v2 = xr[tid + 512];

    __shared__ float red[256];
    red[tid] = v0 + v1 + v2;
    __syncthreads();
    #pragma unroll
    for (int o = 128; o > 0; o >>= 1) {
        if (tid < o) red[tid] += red[tid + o];
        __syncthreads();
    }
    const float mu = red[0] * (1.f / Dc);
    __syncthreads();

    const float d0 = v0 - mu, d1 = v1 - mu, d2 = v2 - mu;
    red[tid] = d0 * d0 + d1 * d1 + d2 * d2;
    __syncthreads();
    #pragma unroll
    for (int o = 128; o > 0; o >>= 1) {
        if (tid < o) red[tid] += red[tid + o];
        __syncthreads();
    }
    const float rstd = rsqrtf(red[0] * (1.f / Dc) + 1e-5f);

    float* orow = out + row * Dc;
    orow[tid]       = d0 * rstd * gamma[tid]       + beta[tid]       + v0;
    orow[tid + 256] = d1 * rstd * gamma[tid + 256] + beta[tid + 256] + v1;
    orow[tid + 512] = d2 * rstd * gamma[tid + 512] + beta[tid + 512] + v2;
}

// ---------------------------------------------------------------------------
extern "C" void kernel_launch(void* const* d_in, const int* in_sizes, int n_in,
                              void* d_out, int out_size)
{
    (void)in_sizes; (void)n_in; (void)out_size;
    const float* x    = (const float*)d_in[0];
    const int*   mask = (const int*)d_in[1];
    const float* Wq = (const float*)d_in[2];
    const float* bq = (const float*)d_in[3];
    const float* Wk = (const float*)d_in[4];
    const float* bk = (const float*)d_in[5];
    const float* Wv = (const float*)d_in[6];
    const float* bv = (const float*)d_in[7];
    const float* gamma = (const float*)d_in[8];
    const float* beta  = (const float*)d_in[9];
    const float* W1 = (const float*)d_in[10];
    const float* b1 = (const float*)d_in[11];
    const float* W2 = (const float*)d_in[12];
    const float* b2 = (const float*)d_in[13];
    float* out = (float*)d_out;

    float *q, *k, *vt, *sc, *mx, *izv, *a, *h, *bb;
    cudaGetSymbolAddress((void**)&q,  g_q);
    cudaGetSymbolAddress((void**)&k,  g_k);
    cudaGetSymbolAddress((void**)&vt, g_vt);
    cudaGetSymbolAddress((void**)&sc, g_sc);
    cudaGetSymbolAddress((void**)&mx, g_m);
    cudaGetSymbolAddress((void**)&izv,g_iz);
    cudaGetSymbolAddress((void**)&a,  g_a);
    cudaGetSymbolAddress((void**)&h,  g_h);
    cudaGetSymbolAddress((void**)&bb, g_b);

    const dim3 blk(256);
    const int MS = Bc * Sc;               // 8192 rows
    const float scale = 1.0f / sqrtf((float)Sc);

    // 1) QKV projections
    {
        dim3 grid(Dc / 128, MS / 128, 1);
        EpiParams pq{q,  bq, nullptr, 0.f};
        EpiParams pk{k,  bk, nullptr, 0.f};
        EpiParams pv{vt, bv, nullptr, 0.f};
        gemm_nt<128,8,2><<<grid, blk>>>(x, Wq, MS, Dc, Ec, 0, 0, pq);
        gemm_nt<128,8,2><<<grid, blk>>>(x, Wk, MS, Dc, Ec, 0, 0, pk);
        gemm_nt<128,8,3><<<grid, blk>>>(x, Wv, MS, Dc, Ec, 0, 0, pv);
    }

    // 2) scores = q @ k^T / sqrt(S), mask -> -1000
    {
        dim3 grid(Sc / 128, Sc / 128, Bc * Hc);
        EpiParams ps{sc, nullptr, mask, scale};
        gemm_nt<128,8,4><<<grid, blk>>>(q, k, Sc, Sc, DHc,
                                        (long)Sc * DHc, (long)Sc * DHc, ps);
    }

    // 3) column-softmax stats (max + inverse sum)
    {
        dim3 grid(Sc / 256, Bc * Hc);
        softmax_stats_kernel<<<grid, 256>>>(sc, mx, izv);
    }

    // 4) o = softmax(sc) @ v with exp applied on-the-fly -> concat heads
    {
        dim3 grid(1, Sc / 128, Bc * Hc);
        gemm_av<<<grid, blk>>>(sc, vt, mx, izv, a);
    }

    // 5) a = LN(a) + a
    ln_residual_kernel<<<MS, 256>>>(a, gamma, beta, a);

    // 6) h = relu(a @ W1^T + b1)
    {
        dim3 grid(Fc / 128, MS / 128, 1);
        EpiParams p1{h, b1, nullptr, 0.f};
        gemm_nt<128,8,1><<<grid, blk>>>(a, W1, MS, Fc, Dc, 0, 0, p1);
    }

    // 7) bb = h @ W2^T + b2
    {
        dim3 grid(Dc / 128, MS / 128, 1);
        EpiParams p2{bb, b2, nullptr, 0.f};
        gemm_nt<128,8,0><<<grid, blk>>>(h, W2, MS, Dc, Fc, 0, 0, p2);
    }

    // 8) out = LN(bb) + bb
    ln_residual_kernel<<<MS, 256>>>(bb, gamma, beta, out);
}

// round 6
// speedup vs baseline: 1.6301x; 1.2430x over previous
#include <cuda_runtime.h>
#include <cuda_bf16.h>
#include <math.h>
#include <stdint.h>

// Problem dims (fixed by the reference)
#define Bc  4
#define Sc  2048
#define Ec  768
#define Dc  768
#define Hc  12
#define DHc 64
#define Fc  3072

#define BK 16

// ---------------- scratch (device globals: allocation-free) ----------------
__device__ float g_q [(size_t)Bc*Hc*Sc*DHc];   // [B,H,S,dh]
__device__ float g_k [(size_t)Bc*Hc*Sc*DHc];   // [B,H,S,dh]
__device__ float g_vt[(size_t)Bc*Hc*DHc*Sc];   // [B,H,dh,S]
__device__ float g_sc[(size_t)Bc*Hc*Sc*Sc];    // [B,H,S,S] masked scores (805 MB)
__device__ float g_m [(size_t)Bc*Hc*Sc];       // per-column max
__device__ float g_iz[(size_t)Bc*Hc*Sc];       // per-column 1/sum(exp)
__device__ float g_a [(size_t)Bc*Sc*Dc];       // attention concat output
__device__ float g_b [(size_t)Bc*Sc*Dc];       // FFN out pre-LN2

// split-bf16 buffers (A pattern = hi,hi,lo ; B pattern = hi,lo,hi)
__device__ __nv_bfloat16 g_xhl [(size_t)Bc*Sc*3*Ec];
__device__ __nv_bfloat16 g_ahl [(size_t)Bc*Sc*3*Dc];
__device__ __nv_bfloat16 g_hhl [(size_t)Bc*Sc*3*Fc];
__device__ __nv_bfloat16 g_wqhl[(size_t)Dc*3*Ec];
__device__ __nv_bfloat16 g_wkhl[(size_t)Dc*3*Ec];
__device__ __nv_bfloat16 g_wvhl[(size_t)Dc*3*Ec];
__device__ __nv_bfloat16 g_w1hl[(size_t)Fc*3*Dc];
__device__ __nv_bfloat16 g_w2hl[(size_t)Dc*3*Fc];

// ======================= warp-MMA helpers (sm_80+ path) =====================
__device__ __forceinline__ uint32_t smem_u32(const void* p) {
    uint32_t a;
    asm("{ .reg .u64 t; cvta.to.shared.u64 t, %1; cvt.u32.u64 %0, t; }" : "=r"(a) : "l"(p));
    return a;
}

__device__ __forceinline__ void ldsm_x4(uint32_t& r0, uint32_t& r1, uint32_t& r2, uint32_t& r3,
                                        uint32_t addr) {
    asm volatile("ldmatrix.sync.aligned.m8n8.x4.shared.b16 {%0,%1,%2,%3}, [%4];"
                 : "=r"(r0), "=r"(r1), "=r"(r2), "=r"(r3) : "r"(addr));
}

__device__ __forceinline__ void mma16816(float* d, const uint32_t* a, uint32_t b0, uint32_t b1) {
    asm volatile("mma.sync.aligned.m16n8k16.row.col.f32.bf16.bf16.f32 "
                 "{%0,%1,%2,%3}, {%4,%5,%6,%7}, {%8,%9}, {%0,%1,%2,%3};"
                 : "+f"(d[0]), "+f"(d[1]), "+f"(d[2]), "+f"(d[3])
                 : "r"(a[0]), "r"(a[1]), "r"(a[2]), "r"(a[3]), "r"(b0), "r"(b1));
}

// ======================= split-bf16 NT GEMM via mma.sync ====================
// C[M,N] = A'[M,Kp] @ B'[N,Kp]^T (bf16 split-encoded, fp32 accumulate).
// Tile 128x128x32(bf16). 256 threads = 8 warps (2 M x 4 N), warp tile 64x32.
// EPI: 0 = +bias -> outF[m*N+n]
//      1 = relu(+bias) -> split triple (hi,hi,lo) into outH [m, 3N]
//      2 = QK scatter  out[b,h,s,d]  (+bias)
//      3 = V  scatter  out[b,h,d,s]  (+bias)
#define LDSH 40   // bf16 elems per smem row (80 B pitch; conflict-free ldmatrix)

template<int EPI>
__global__ void __launch_bounds__(256, 2)
gemm_mma(const __nv_bfloat16* __restrict__ A, const __nv_bfloat16* __restrict__ Bw,
         int N, int Kp, const float* __restrict__ bias,
         float* __restrict__ outF, __nv_bfloat16* __restrict__ outH)
{
    __shared__ __nv_bfloat16 sA[2][128 * LDSH];
    __shared__ __nv_bfloat16 sB[2][128 * LDSH];

    const int tid  = threadIdx.x;
    const int wid  = tid >> 5;
    const int lane = tid & 31;
    const int m0   = blockIdx.y * 128;
    const int n0   = blockIdx.x * 128;
    const int wm   = (wid & 1) * 64;      // warp M offset in tile
    const int wn   = (wid >> 1) * 32;     // warp N offset in tile

    const uint32_t sAu = smem_u32(sA);
    const uint32_t sBu = smem_u32(sB);
    const uint32_t bufBytes = 128 * LDSH * 2;

    float acc[4][4][4];
    #pragma unroll
    for (int i = 0; i < 4; ++i)
        #pragma unroll
        for (int j = 0; j < 4; ++j)
            #pragma unroll
            for (int p = 0; p < 4; ++p) acc[i][j][p] = 0.f;

    const int nk = Kp / 32;

    auto stage = [&](int s, int kt) {
        const int kc = kt * 32;
        #pragma unroll
        for (int i = 0; i < 2; ++i) {
            const int id = tid + i * 256;          // 0..511
            const int r  = id >> 2;                // 0..127
            const int c  = (id & 3) * 8;           // 0,8,16,24 (bf16)
            uint4 va = *reinterpret_cast<const uint4*>(&A [(size_t)(m0 + r) * Kp + kc + c]);
            uint4 vb = *reinterpret_cast<const uint4*>(&Bw[(size_t)(n0 + r) * Kp + kc + c]);
            *reinterpret_cast<uint4*>(&sA[s][r * LDSH + c]) = va;
            *reinterpret_cast<uint4*>(&sB[s][r * LDSH + c]) = vb;
        }
    };

    stage(0, 0);
    __syncthreads();

    const int lrow = lane & 15;
    const int lcol = (lane >> 4) * 8;

    for (int kt = 0; kt < nk; ++kt) {
        const int cur = kt & 1;
        if (kt + 1 < nk) stage(cur ^ 1, kt + 1);

        const uint32_t aBase = sAu + cur * bufBytes;
        const uint32_t bBase = sBu + cur * bufBytes;

        #pragma unroll
        for (int ks = 0; ks < 32; ks += 16) {
            uint32_t a[4][4];
            #pragma unroll
            for (int mi = 0; mi < 4; ++mi) {
                const uint32_t ad = aBase + (uint32_t)(wm + mi * 16 + lrow) * (LDSH * 2)
                                          + (uint32_t)(ks + lcol) * 2;
                ldsm_x4(a[mi][0], a[mi][1], a[mi][2], a[mi][3], ad);
            }
            uint32_t b[2][4];
            #pragma unroll
            for (int bj = 0; bj < 2; ++bj) {
                const uint32_t bd = bBase + (uint32_t)(wn + bj * 16 + lrow) * (LDSH * 2)
                                          + (uint32_t)(ks + lcol) * 2;
                ldsm_x4(b[bj][0], b[bj][1], b[bj][2], b[bj][3], bd);
            }
            #pragma unroll
            for (int mi = 0; mi < 4; ++mi)
                #pragma unroll
                for (int nj = 0; nj < 4; ++nj)
                    mma16816(acc[mi][nj], a[mi], b[nj >> 1][nj & 1], b[nj >> 1][(nj & 1) + 2]);
        }
        __syncthreads();
    }

    // ---------------- epilogue ----------------
    const int r4 = lane >> 2;            // 0..7
    const int c2 = (lane & 3) * 2;       // 0,2,4,6

    #pragma unroll
    for (int mi = 0; mi < 4; ++mi) {
        #pragma unroll
        for (int half = 0; half < 2; ++half) {
            const int m = m0 + wm + mi * 16 + r4 + half * 8;
            #pragma unroll
            for (int nj = 0; nj < 4; ++nj) {
                const int n = n0 + wn + nj * 8 + c2;
                const float v0 = acc[mi][nj][half * 2]     + ((EPI == 1 || bias) ? bias[n]     : 0.f);
                const float v1 = acc[mi][nj][half * 2 + 1] + ((EPI == 1 || bias) ? bias[n + 1] : 0.f);
                if (EPI == 0) {
                    *reinterpret_cast<float2*>(&outF[(size_t)m * N + n]) = make_float2(v0, v1);
                } else if (EPI == 1) {
                    const float u0 = fmaxf(v0, 0.f), u1 = fmaxf(v1, 0.f);
                    const __nv_bfloat16 h0 = __float2bfloat16(u0);
                    const __nv_bfloat16 h1 = __float2bfloat16(u1);
                    const __nv_bfloat16 l0 = __float2bfloat16(u0 - __bfloat162float(h0));
                    const __nv_bfloat16 l1 = __float2bfloat16(u1 - __bfloat162float(h1));
                    const uint32_t hw = (uint32_t)__bfloat16_as_ushort(h0) |
                                        ((uint32_t)__bfloat16_as_ushort(h1) << 16);
                    const uint32_t lw = (uint32_t)__bfloat16_as_ushort(l0) |
                                        ((uint32_t)__bfloat16_as_ushort(l1) << 16);
                    const size_t rb = (size_t)m * (3 * N);
                    *reinterpret_cast<uint32_t*>(&outH[rb + n])         = hw;
                    *reinterpret_cast<uint32_t*>(&outH[rb + N + n])     = hw;
                    *reinterpret_cast<uint32_t*>(&outH[rb + 2 * N + n]) = lw;
                } else if (EPI == 2) {
                    const int b = m >> 11, s = m & 2047;
                    const int h = n >> 6,  d = n & 63;
                    *reinterpret_cast<float2*>(
                        &outF[(((size_t)b * Hc + h) * Sc + s) * DHc + d]) = make_float2(v0, v1);
                } else if (EPI == 3) {
                    const int b = m >> 11, s = m & 2047;
                    const int h = n >> 6,  d = n & 63;
                    outF[(((size_t)b * Hc + h) * DHc + d)     * Sc + s] = v0;
                    outF[(((size_t)b * Hc + h) * DHc + d + 1) * Sc + s] = v1;
                }
            }
        }
    }
}

// ======================= split conversion kernels ===========================
// A pattern: (hi, hi, lo) ; B pattern: (hi, lo, hi)
template<int PATB>
__global__ void cvt_split(const float* __restrict__ src, __nv_bfloat16* __restrict__ dst, int K)
{
    const size_t i = (size_t)blockIdx.x * blockDim.x + threadIdx.x;
    const size_t rw = i / K, c = i % K;
    const float v = src[i];
    const __nv_bfloat16 hi = __float2bfloat16(v);
    const __nv_bfloat16 lo = __float2bfloat16(v - __bfloat162float(hi));
    __nv_bfloat16* row = dst + rw * (size_t)(3 * K);
    row[c]         = hi;
    row[K + c]     = PATB ? lo : hi;
    row[2 * K + c] = PATB ? hi : lo;
}

// ======================= SIMT attention kernels (R4-proven) =================
__global__ void __launch_bounds__(256)
gemm_scores(const float* __restrict__ Q, const float* __restrict__ Kt,
            const int* __restrict__ mask, float* __restrict__ SC, float scale)
{
    const int z = blockIdx.z;
    const float* A  = Q  + (long)z * Sc * DHc;
    const float* Bm = Kt + (long)z * Sc * DHc;

    __shared__ float As[2][BK][128];
    __shared__ float Bs[2][BK][128];

    const int tid = threadIdx.x;
    const int tx  = tid & 15;
    const int ty  = tid >> 4;
    const int m0  = blockIdx.y * 128;
    const int n0  = blockIdx.x * 128;

    const int lr = tid >> 2;
    const int lc = (tid & 3) * 4;

    float acc[8][8];
    #pragma unroll
    for (int i = 0; i < 8; ++i)
        #pragma unroll
        for (int j = 0; j < 8; ++j) acc[i][j] = 0.f;

    const int nk = DHc / BK;   // 4

    {
        float4 a0 = *reinterpret_cast<const float4*>(&A [(long)(m0 + lr)      * DHc + lc]);
        float4 a1 = *reinterpret_cast<const float4*>(&A [(long)(m0 + lr + 64) * DHc + lc]);
        As[0][lc+0][lr] = a0.x; As[0][lc+1][lr] = a0.y; As[0][lc+2][lr] = a0.z; As[0][lc+3][lr] = a0.w;
        As[0][lc+0][lr+64] = a1.x; As[0][lc+1][lr+64] = a1.y; As[0][lc+2][lr+64] = a1.z; As[0][lc+3][lr+64] = a1.w;
        float4 b0 = *reinterpret_cast<const float4*>(&Bm[(long)(n0 + lr) * DHc + lc]);
        float4 b1 = *reinterpret_cast<const float4*>(&Bm[(long)(n0 + lr + 64) * DHc + lc]);
        Bs[0][lc+0][lr] = b0.x; Bs[0][lc+1][lr] = b0.y; Bs[0][lc+2][lr] = b0.z; Bs[0][lc+3][lr] = b0.w;
        Bs[0][lc+0][lr+64] = b1.x; Bs[0][lc+1][lr+64] = b1.y; Bs[0][lc+2][lr+64] = b1.z; Bs[0][lc+3][lr+64] = b1.w;
    }
    __syncthreads();

    for (int kt = 0; kt < nk; ++kt) {
        const int cur = kt & 1, nxt = cur ^ 1;
        float4 pa0, pa1, pb0, pb1;
        const bool has_next = (kt + 1 < nk);
        if (has_next) {
            const int k0 = (kt + 1) * BK;
            pa0 = *reinterpret_cast<const float4*>(&A [(long)(m0 + lr)      * DHc + k0 + lc]);
            pa1 = *reinterpret_cast<const float4*>(&A [(long)(m0 + lr + 64) * DHc + k0 + lc]);
            pb0 = *reinterpret_cast<const float4*>(&Bm[(long)(n0 + lr) * DHc + k0 + lc]);
            pb1 = *reinterpret_cast<const float4*>(&Bm[(long)(n0 + lr + 64) * DHc + k0 + lc]);
        }

        #pragma unroll
        for (int k = 0; k < BK; ++k) {
            float ra[8], rb[8];
            const float4* a4 = reinterpret_cast<const float4*>(&As[cur][k][ty * 8]);
            float4 av0 = a4[0], av1 = a4[1];
            ra[0]=av0.x; ra[1]=av0.y; ra[2]=av0.z; ra[3]=av0.w;
            ra[4]=av1.x; ra[5]=av1.y; ra[6]=av1.z; ra[7]=av1.w;
            const float4* b4 = reinterpret_cast<const float4*>(&Bs[cur][k][tx * 8]);
            float4 bv0 = b4[0], bv1 = b4[1];
            rb[0]=bv0.x; rb[1]=bv0.y; rb[2]=bv0.z; rb[3]=bv0.w;
            rb[4]=bv1.x; rb[5]=bv1.y; rb[6]=bv1.z; rb[7]=bv1.w;
            #pragma unroll
            for (int i = 0; i < 8; ++i)
                #pragma unroll
                for (int j = 0; j < 8; ++j) acc[i][j] = fmaf(ra[i], rb[j], acc[i][j]);
        }

        if (has_next) {
            As[nxt][lc+0][lr] = pa0.x; As[nxt][lc+1][lr] = pa0.y; As[nxt][lc+2][lr] = pa0.z; As[nxt][lc+3][lr] = pa0.w;
            As[nxt][lc+0][lr+64] = pa1.x; As[nxt][lc+1][lr+64] = pa1.y; As[nxt][lc+2][lr+64] = pa1.z; As[nxt][lc+3][lr+64] = pa1.w;
            Bs[nxt][lc+0][lr] = pb0.x; Bs[nxt][lc+1][lr] = pb0.y; Bs[nxt][lc+2][lr] = pb0.z; Bs[nxt][lc+3][lr] = pb0.w;
            Bs[nxt][lc+0][lr+64] = pb1.x; Bs[nxt][lc+1][lr+64] = pb1.y; Bs[nxt][lc+2][lr+64] = pb1.z; Bs[nxt][lc+3][lr+64] = pb1.w;
            __syncthreads();
        }
    }

    const int b = z / Hc;
    #pragma unroll
    for (int i = 0; i < 8; ++i) {
        const int m = m0 + ty * 8 + i;
        #pragma unroll
        for (int j = 0; j < 8; j += 4) {
            const int n = n0 + tx * 8 + j;
            const int4 mk = *reinterpret_cast<const int4*>(&mask[((long)b * Sc + m) * Sc + n]);
            float4 v;
            v.x = mk.x ? -1000.f : acc[i][j]   * scale;
            v.y = mk.y ? -1000.f : acc[i][j+1] * scale;
            v.z = mk.z ? -1000.f : acc[i][j+2] * scale;
            v.w = mk.w ? -1000.f : acc[i][j+3] * scale;
            *reinterpret_cast<float4*>(&SC[((long)z * Sc + m) * Sc + n]) = v;
        }
    }
}

__global__ void __launch_bounds__(256)
gemm_av(const float* __restrict__ SCp, const float* __restrict__ VT,
        const float* __restrict__ Mx, const float* __restrict__ IZ,
        float* __restrict__ out)
{
    const int z = blockIdx.z;
    const float* A  = SCp + (long)z * Sc * Sc;
    const float* Bm = VT  + (long)z * DHc * Sc;
    const float* mz = Mx  + (long)z * Sc;
    const float* iz = IZ  + (long)z * Sc;

    __shared__ float As[2][BK][128];
    __shared__ float Bs[2][BK][64];

    const int tid = threadIdx.x;
    const int tx  = tid & 15;
    const int ty  = tid >> 4;
    const int m0  = blockIdx.y * 128;

    const int lr = tid >> 2;
    const int lc = (tid & 3) * 4;

    float acc[8][4];
    #pragma unroll
    for (int i = 0; i < 8; ++i)
        #pragma unroll
        for (int j = 0; j < 4; ++j) acc[i][j] = 0.f;

    const int nk = Sc / BK;

    auto loadA = [&](int k0, float4& o0, float4& o1) {
        const float4 mv = *reinterpret_cast<const float4*>(&mz[k0 + lc]);
        const float4 zv = *reinterpret_cast<const float4*>(&iz[k0 + lc]);
        float4 a0 = *reinterpret_cast<const float4*>(&A[(long)(m0 + lr)      * Sc + k0 + lc]);
        float4 a1 = *reinterpret_cast<const float4*>(&A[(long)(m0 + lr + 64) * Sc + k0 + lc]);
        o0.x = __expf(a0.x - mv.x) * zv.x; o0.y = __expf(a0.y - mv.y) * zv.y;
        o0.z = __expf(a0.z - mv.z) * zv.z; o0.w = __expf(a0.w - mv.w) * zv.w;
        o1.x = __expf(a1.x - mv.x) * zv.x; o1.y = __expf(a1.y - mv.y) * zv.y;
        o1.z = __expf(a1.z - mv.z) * zv.z; o1.w = __expf(a1.w - mv.w) * zv.w;
    };

    {
        float4 a0, a1;
        loadA(0, a0, a1);
        As[0][lc+0][lr] = a0.x; As[0][lc+1][lr] = a0.y; As[0][lc+2][lr] = a0.z; As[0][lc+3][lr] = a0.w;
        As[0][lc+0][lr+64] = a1.x; As[0][lc+1][lr+64] = a1.y; As[0][lc+2][lr+64] = a1.z; As[0][lc+3][lr+64] = a1.w;
        float4 b0 = *reinterpret_cast<const float4*>(&Bm[(long)lr * Sc + lc]);
        Bs[0][lc+0][lr] = b0.x; Bs[0][lc+1][lr] = b0.y; Bs[0][lc+2][lr] = b0.z; Bs[0][lc+3][lr] = b0.w;
    }
    __syncthreads();

    for (int kt = 0; kt < nk; ++kt) {
        const int cur = kt & 1, nxt = cur ^ 1;
        float4 pa0, pa1, pb0;
        const bool has_next = (kt + 1 < nk);
        if (has_next) {
            const int k0 = (kt + 1) * BK;
            loadA(k0, pa0, pa1);
            pb0 = *reinterpret_cast<const float4*>(&Bm[(long)lr * Sc + k0 + lc]);
        }

        #pragma unroll
        for (int k = 0; k < BK; ++k) {
            float ra[8], rb[4];
            const float4* a4 = reinterpret_cast<const float4*>(&As[cur][k][ty * 8]);
            float4 av0 = a4[0], av1 = a4[1];
            ra[0]=av0.x; ra[1]=av0.y; ra[2]=av0.z; ra[3]=av0.w;
            ra[4]=av1.x; ra[5]=av1.y; ra[6]=av1.z; ra[7]=av1.w;
            const float4 bv = reinterpret_cast<const float4*>(&Bs[cur][k][tx * 4])[0];
            rb[0]=bv.x; rb[1]=bv.y; rb[2]=bv.z; rb[3]=bv.w;
            #pragma unroll
            for (int i = 0; i < 8; ++i)
                #pragma unroll
                for (int j = 0; j < 4; ++j) acc[i][j] = fmaf(ra[i], rb[j], acc[i][j]);
        }

        if (has_next) {
            As[nxt][lc+0][lr] = pa0.x; As[nxt][lc+1][lr] = pa0.y; As[nxt][lc+2][lr] = pa0.z; As[nxt][lc+3][lr] = pa0.w;
            As[nxt][lc+0][lr+64] = pa1.x; As[nxt][lc+1][lr+64] = pa1.y; As[nxt][lc+2][lr+64] = pa1.z; As[nxt][lc+3][lr+64] = pa1.w;
            Bs[nxt][lc+0][lr] = pb0.x; Bs[nxt][lc+1][lr] = pb0.y; Bs[nxt][lc+2][lr] = pb0.z; Bs[nxt][lc+3][lr] = pb0.w;
            __syncthreads();
        }
    }

    const int b = z / Hc, h = z % Hc;
    #pragma unroll
    for (int i = 0; i < 8; ++i) {
        const int s = m0 + ty * 8 + i;
        const int d = tx * 4;
        float4 v = make_float4(acc[i][0], acc[i][1], acc[i][2], acc[i][3]);
        *reinterpret_cast<float4*>(&out[((long)b * Sc + s) * Dc + h * DHc + d]) = v;
    }
}

__global__ void softmax_stats_kernel(const float* __restrict__ sc,
                                     float* __restrict__ Mx, float* __restrict__ IZ)
{
    const int t = blockIdx.x * blockDim.x + threadIdx.x;
    const int z = blockIdx.y;
    const size_t base = (size_t)z * Sc * Sc;

    float m = -3.4e38f, sum = 0.f;
    for (int s = 0; s < Sc; ++s) {
        float x = sc[base + (size_t)s * Sc + t];
        if (x > m) { sum = sum * __expf(m - x) + 1.f; m = x; }
        else       { sum += __expf(x - m); }
    }
    Mx[(size_t)z * Sc + t] = m;
    IZ[(size_t)z * Sc + t] = 1.f / sum;
}

// LN + residual. SPLIT=0: fp32 out. SPLIT=1: (hi,hi,lo) bf16 triple out.
template<int SPLIT>
__global__ void ln_residual_kernel(const float* __restrict__ in,
                                   const float* __restrict__ gamma,
                                   const float* __restrict__ beta,
                                   float* __restrict__ out,
                                   __nv_bfloat16* __restrict__ outH)
{
    const size_t row = blockIdx.x;
    const float* xr = in + row * Dc;
    const int tid = threadIdx.x;

    const float v0 = xr[tid], v1 = xr[tid + 256], v2 = xr[tid + 512];

    __shared__ float red[256];
    red[tid] = v0 + v1 + v2;
    __syncthreads();
    #pragma unroll
    for (int o = 128; o > 0; o >>= 1) {
        if (tid < o) red[tid] += red[tid + o];
        __syncthreads();
    }
    const float mu = red[0] * (1.f / Dc);
    __syncthreads();

    const float d0 = v0 - mu, d1 = v1 - mu, d2 = v2 - mu;
    red[tid] = d0 * d0 + d1 * d1 + d2 * d2;
    __syncthreads();
    #pragma unroll
    for (int o = 128; o > 0; o >>= 1) {
        if (tid < o) red[tid] += red[tid + o];
        __syncthreads();
    }
    const float rstd = rsqrtf(red[0] * (1.f / Dc) + 1e-5f);

    const float o0 = d0 * rstd * gamma[tid]       + beta[tid]       + v0;
    const float o1 = d1 * rstd * gamma[tid + 256] + beta[tid + 256] + v1;
    const float o2 = d2 * rstd * gamma[tid + 512] + beta[tid + 512] + v2;

    if (SPLIT == 0) {
        float* orow = out + row * Dc;
        orow[tid] = o0; orow[tid + 256] = o1; orow[tid + 512] = o2;
    } else {
        __nv_bfloat16* orow = outH + row * (size_t)(3 * Dc);
        #pragma unroll
        for (int u = 0; u < 3; ++u) {
            const float v = (u == 0) ? o0 : (u == 1) ? o1 : o2;
            const int  c = tid + u * 256;
            const __nv_bfloat16 hi = __float2bfloat16(v);
            const __nv_bfloat16 lo = __float2bfloat16(v - __bfloat162float(hi));
            orow[c] = hi; orow[Dc + c] = hi; orow[2 * Dc + c] = lo;
        }
    }
}

// ---------------------------------------------------------------------------
extern "C" void kernel_launch(void* const* d_in, const int* in_sizes, int n_in,
                              void* d_out, int out_size)
{
    (void)in_sizes; (void)n_in; (void)out_size;
    const float* x    = (const float*)d_in[0];
    const int*   mask = (const int*)d_in[1];
    const float* Wq = (const float*)d_in[2];
    const float* bq = (const float*)d_in[3];
    const float* Wk = (const float*)d_in[4];
    const float* bk = (const float*)d_in[5];
    const float* Wv = (const float*)d_in[6];
    const float* bv = (const float*)d_in[7];
    const float* gamma = (const float*)d_in[8];
    const float* beta  = (const float*)d_in[9];
    const float* W1 = (const float*)d_in[10];
    const float* b1 = (const float*)d_in[11];
    const float* W2 = (const float*)d_in[12];
    const float* b2 = (const float*)d_in[13];
    float* out = (float*)d_out;

    float *q, *k, *vt, *sc, *mx, *izv, *a, *bb;
    cudaGetSymbolAddress((void**)&q,   g_q);
    cudaGetSymbolAddress((void**)&k,   g_k);
    cudaGetSymbolAddress((void**)&vt,  g_vt);
    cudaGetSymbolAddress((void**)&sc,  g_sc);
    cudaGetSymbolAddress((void**)&mx,  g_m);
    cudaGetSymbolAddress((void**)&izv, g_iz);
    cudaGetSymbolAddress((void**)&a,   g_a);
    cudaGetSymbolAddress((void**)&bb,  g_b);

    __nv_bfloat16 *xhl, *ahl, *hhl, *wqhl, *wkhl, *wvhl, *w1hl, *w2hl;
    cudaGetSymbolAddress((void**)&xhl,  g_xhl);
    cudaGetSymbolAddress((void**)&ahl,  g_ahl);
    cudaGetSymbolAddress((void**)&hhl,  g_hhl);
    cudaGetSymbolAddress((void**)&wqhl, g_wqhl);
    cudaGetSymbolAddress((void**)&wkhl, g_wkhl);
    cudaGetSymbolAddress((void**)&wvhl, g_wvhl);
    cudaGetSymbolAddress((void**)&w1hl, g_w1hl);
    cudaGetSymbolAddress((void**)&w2hl, g_w2hl);

    const int MS = Bc * Sc;               // 8192
    const float scale = 1.0f / sqrtf((float)Sc);

    // 0) split conversions
    cvt_split<0><<<(MS * Ec) / 256, 256>>>(x,  xhl,  Ec);
    cvt_split<1><<<(Dc * Ec) / 256, 256>>>(Wq, wqhl, Ec);
    cvt_split<1><<<(Dc * Ec) / 256, 256>>>(Wk, wkhl, Ec);
    cvt_split<1><<<(Dc * Ec) / 256, 256>>>(Wv, wvhl, Ec);
    cvt_split<1><<<(Fc * Dc) / 256, 256>>>(W1, w1hl, Dc);
    cvt_split<1><<<(Dc * Fc) / 256, 256>>>(W2, w2hl, Fc);

    // 1) QKV projections (tensor cores)
    {
        dim3 grid(Dc / 128, MS / 128);
        gemm_mma<2><<<grid, 256>>>(xhl, wqhl, Dc, 3 * Ec, bq, q,  nullptr);
        gemm_mma<2><<<grid, 256>>>(xhl, wkhl, Dc, 3 * Ec, bk, k,  nullptr);
        gemm_mma<3><<<grid, 256>>>(xhl, wvhl, Dc, 3 * Ec, bv, vt, nullptr);
    }

    // 2) scores = q @ k^T / sqrt(S), mask -> -1000
    {
        dim3 grid(Sc / 128, Sc / 128, Bc * Hc);
        gemm_scores<<<grid, 256>>>(q, k, mask, sc, scale);
    }

    // 3) column-softmax stats
    {
        dim3 grid(Sc / 256, Bc * Hc);
        softmax_stats_kernel<<<grid, 256>>>(sc, mx, izv);
    }

    // 4) o = softmax(sc) @ v -> concat heads (fp32)
    {
        dim3 grid(1, Sc / 128, Bc * Hc);
        gemm_av<<<grid, 256>>>(sc, vt, mx, izv, a);
    }

    // 5) a = LN(a) + a  -> split bf16 triple for FFN1
    ln_residual_kernel<1><<<MS, 256>>>(a, gamma, beta, nullptr, ahl);

    // 6) h = relu(a @ W1^T + b1) -> split triple (tensor cores)
    {
        dim3 grid(Fc / 128, MS / 128);
        gemm_mma<1><<<grid, 256>>>(ahl, w1hl, Fc, 3 * Dc, b1, nullptr, hhl);
    }

    // 7) bb = h @ W2^T + b2 (tensor cores)
    {
        dim3 grid(Dc / 128, MS / 128);
        gemm_mma<0><<<grid, 256>>>(hhl, w2hl, Dc, 3 * Fc, b2, bb, nullptr);
    }

    // 8) out = LN(bb) + bb
    ln_residual_kernel<0><<<MS, 256>>>(bb, gamma, beta, out, nullptr);
}

// round 7
// speedup vs baseline: 1.9337x; 1.1862x over previous
#include <cuda_runtime.h>
#include <cuda_bf16.h>
#include <math.h>
#include <stdint.h>

// Problem dims (fixed by the reference)
#define Bc  4
#define Sc  2048
#define Ec  768
#define Dc  768
#define Hc  12
#define DHc 64
#define Fc  3072

#define BK 16
#define LDSH 40                      // bf16 per smem row (80 B pitch)
#define STAGE_BYTES (128 * LDSH * 2) // one matrix, one stage = 10240 B
#define GEMM_SMEM (3 * 2 * STAGE_BYTES)

// ---------------- scratch (device globals: allocation-free) ----------------
__device__ float g_vt[(size_t)Bc*Hc*DHc*Sc];   // [B,H,dh,S]
__device__ float g_sc[(size_t)Bc*Hc*Sc*Sc];    // [B,H,S,S] masked scores
__device__ float g_m [(size_t)Bc*Hc*Sc];
__device__ float g_iz[(size_t)Bc*Hc*Sc];
__device__ float g_a [(size_t)Bc*Sc*Dc];
__device__ float g_b [(size_t)Bc*Sc*Dc];

// split-bf16 buffers (A pattern = hi,hi,lo ; B pattern = hi,lo,hi)
__device__ __nv_bfloat16 g_xhl [(size_t)Bc*Sc*3*Ec];
__device__ __nv_bfloat16 g_ahl [(size_t)Bc*Sc*3*Dc];
__device__ __nv_bfloat16 g_hhl [(size_t)Bc*Sc*3*Fc];
__device__ __nv_bfloat16 g_qs  [(size_t)Bc*Hc*Sc*3*DHc];  // q split (A pat)
__device__ __nv_bfloat16 g_ks  [(size_t)Bc*Hc*Sc*3*DHc];  // k split (B pat)
__device__ __nv_bfloat16 g_wqhl[(size_t)Dc*3*Ec];
__device__ __nv_bfloat16 g_wkhl[(size_t)Dc*3*Ec];
__device__ __nv_bfloat16 g_wvhl[(size_t)Dc*3*Ec];
__device__ __nv_bfloat16 g_w1hl[(size_t)Fc*3*Dc];
__device__ __nv_bfloat16 g_w2hl[(size_t)Dc*3*Fc];

// ======================= warp-MMA helpers ===================================
__device__ __forceinline__ uint32_t smem_u32(const void* p) {
    uint32_t a;
    asm("{ .reg .u64 t; cvta.to.shared.u64 t, %1; cvt.u32.u64 %0, t; }" : "=r"(a) : "l"(p));
    return a;
}
__device__ __forceinline__ void ldsm_x4(uint32_t& r0, uint32_t& r1, uint32_t& r2, uint32_t& r3,
                                        uint32_t addr) {
    asm volatile("ldmatrix.sync.aligned.m8n8.x4.shared.b16 {%0,%1,%2,%3}, [%4];"
                 : "=r"(r0), "=r"(r1), "=r"(r2), "=r"(r3) : "r"(addr));
}
__device__ __forceinline__ void mma16816(float* d, const uint32_t* a, uint32_t b0, uint32_t b1) {
    asm volatile("mma.sync.aligned.m16n8k16.row.col.f32.bf16.bf16.f32 "
                 "{%0,%1,%2,%3}, {%4,%5,%6,%7}, {%8,%9}, {%0,%1,%2,%3};"
                 : "+f"(d[0]), "+f"(d[1]), "+f"(d[2]), "+f"(d[3])
                 : "r"(a[0]), "r"(a[1]), "r"(a[2]), "r"(a[3]), "r"(b0), "r"(b1));
}
#define CP_ASYNC16(dst, src) \
    asm volatile("cp.async.cg.shared.global [%0], [%1], 16;" :: "r"(dst), "l"(src))
#define CP_COMMIT() asm volatile("cp.async.commit_group;")
#define CP_WAIT1()  asm volatile("cp.async.wait_group 1;")

// ======================= split-bf16 NT GEMM via mma.sync ====================
// C[M,N] = A'[M,Kp] @ B'[N,Kp]^T, batched via blockIdx.z (strideA/strideB).
// Tile 128x128x32(bf16), 3-stage cp.async pipeline, 8 warps (2Mx4N), 64x32.
// EPI: 0 = +bias -> outF[m*N+n]
//      1 = relu(+bias) -> split triple (hi,hi,lo) into outH [m, 3N]
//      3 = V scatter  outF[b,h,d,s]  (+bias)
//      4 = scores: mask -> -1000 else acc*scale; outF[z,m,n]
//      5 = q split scatter: (hi,hi,lo) into outH[(b,h,s), 3*64]  (+bias)
//      6 = k split scatter: (hi,lo,hi) into outH[(b,h,s), 3*64]  (+bias)
template<int EPI>
__global__ void __launch_bounds__(256, 2)
gemm_mma(const __nv_bfloat16* __restrict__ A, const __nv_bfloat16* __restrict__ Bw,
         int N, int Kp, long strideA, long strideB,
         const float* __restrict__ bias, const int* __restrict__ mask, float scale,
         float* __restrict__ outF, __nv_bfloat16* __restrict__ outH)
{
    extern __shared__ char dynsm[];

    const int z = blockIdx.z;
    A  += (size_t)z * strideA;
    Bw += (size_t)z * strideB;

    const int tid  = threadIdx.x;
    const int wid  = tid >> 5;
    const int lane = tid & 31;
    const int m0   = blockIdx.y * 128;
    const int n0   = blockIdx.x * 128;
    const int wm   = (wid & 1) * 64;
    const int wn   = (wid >> 1) * 32;

    const uint32_t smBase = smem_u32(dynsm);

    float acc[4][4][4];
    #pragma unroll
    for (int i = 0; i < 4; ++i)
        #pragma unroll
        for (int j = 0; j < 4; ++j)
            #pragma unroll
            for (int p = 0; p < 4; ++p) acc[i][j][p] = 0.f;

    const int nk = Kp / 32;

    auto stage = [&](int s, int kt) {
        const int kc = kt * 32;
        const uint32_t base = smBase + s * (2 * STAGE_BYTES);
        #pragma unroll
        for (int i = 0; i < 2; ++i) {
            const int id = tid + i * 256;
            const int r  = id >> 2;
            const int c  = (id & 3) * 8;
            const uint32_t dA = base + (uint32_t)(r * 80 + c * 2);
            const uint32_t dB = dA + STAGE_BYTES;
            CP_ASYNC16(dA, &A [(size_t)(m0 + r) * Kp + kc + c]);
            CP_ASYNC16(dB, &Bw[(size_t)(n0 + r) * Kp + kc + c]);
        }
    };

    stage(0, 0); CP_COMMIT();
    stage(1, 1); CP_COMMIT();

    const int lrow = lane & 15;
    const int lcol = (lane >> 4) * 8;

    for (int kt = 0; kt < nk; ++kt) {
        CP_WAIT1();
        __syncthreads();

        const uint32_t aBase = smBase + (kt % 3) * (2 * STAGE_BYTES);
        const uint32_t bBase = aBase + STAGE_BYTES;

        #pragma unroll
        for (int ks = 0; ks < 32; ks += 16) {
            uint32_t a[4][4];
            #pragma unroll
            for (int mi = 0; mi < 4; ++mi) {
                const uint32_t ad = aBase + (uint32_t)(wm + mi * 16 + lrow) * 80
                                          + (uint32_t)(ks + lcol) * 2;
                ldsm_x4(a[mi][0], a[mi][1], a[mi][2], a[mi][3], ad);
            }
            uint32_t b[2][4];
            #pragma unroll
            for (int bj = 0; bj < 2; ++bj) {
                const uint32_t bd = bBase + (uint32_t)(wn + bj * 16 + lrow) * 80
                                          + (uint32_t)(ks + lcol) * 2;
                ldsm_x4(b[bj][0], b[bj][1], b[bj][2], b[bj][3], bd);
            }
            #pragma unroll
            for (int mi = 0; mi < 4; ++mi)
                #pragma unroll
                for (int nj = 0; nj < 4; ++nj)
                    mma16816(acc[mi][nj], a[mi], b[nj >> 1][nj & 1], b[nj >> 1][(nj & 1) + 2]);
        }

        if (kt + 2 < nk) stage((kt + 2) % 3, kt + 2);
        CP_COMMIT();
    }

    // ---------------- epilogue ----------------
    const int r4 = lane >> 2;
    const int c2 = (lane & 3) * 2;

    #pragma unroll
    for (int mi = 0; mi < 4; ++mi) {
        #pragma unroll
        for (int half = 0; half < 2; ++half) {
            const int m = m0 + wm + mi * 16 + r4 + half * 8;
            #pragma unroll
            for (int nj = 0; nj < 4; ++nj) {
                const int n = n0 + wn + nj * 8 + c2;
                float v0 = acc[mi][nj][half * 2];
                float v1 = acc[mi][nj][half * 2 + 1];
                if (EPI != 4) { v0 += bias[n]; v1 += bias[n + 1]; }
                if (EPI == 0) {
                    *reinterpret_cast<float2*>(&outF[(size_t)m * N + n]) = make_float2(v0, v1);
                } else if (EPI == 1) {
                    const float u0 = fmaxf(v0, 0.f), u1 = fmaxf(v1, 0.f);
                    const __nv_bfloat16 h0 = __float2bfloat16(u0);
                    const __nv_bfloat16 h1 = __float2bfloat16(u1);
                    const __nv_bfloat16 l0 = __float2bfloat16(u0 - __bfloat162float(h0));
                    const __nv_bfloat16 l1 = __float2bfloat16(u1 - __bfloat162float(h1));
                    const uint32_t hw = (uint32_t)__bfloat16_as_ushort(h0) |
                                        ((uint32_t)__bfloat16_as_ushort(h1) << 16);
                    const uint32_t lw = (uint32_t)__bfloat16_as_ushort(l0) |
                                        ((uint32_t)__bfloat16_as_ushort(l1) << 16);
                    const size_t rb = (size_t)m * (3 * N);
                    *reinterpret_cast<uint32_t*>(&outH[rb + n])         = hw;
                    *reinterpret_cast<uint32_t*>(&outH[rb + N + n])     = hw;
                    *reinterpret_cast<uint32_t*>(&outH[rb + 2 * N + n]) = lw;
                } else if (EPI == 3) {
                    const int b = m >> 11, s = m & 2047;
                    const int h = n >> 6,  d = n & 63;
                    outF[(((size_t)b * Hc + h) * DHc + d)     * Sc + s] = v0;
                    outF[(((size_t)b * Hc + h) * DHc + d + 1) * Sc + s] = v1;
                } else if (EPI == 4) {
                    const int bq = z / Hc;
                    const int2 mk = *reinterpret_cast<const int2*>(
                        &mask[((size_t)bq * Sc + m) * Sc + n]);
                    float2 v;
                    v.x = mk.x ? -1000.f : v0 * scale;
                    v.y = mk.y ? -1000.f : v1 * scale;
                    *reinterpret_cast<float2*>(&outF[((size_t)z * Sc + m) * Sc + n]) = v;
                } else { // EPI 5 / 6
                    const int b = m >> 11, s = m & 2047;
                    const int h = n >> 6,  d = n & 63;
                    const __nv_bfloat16 h0 = __float2bfloat16(v0);
                    const __nv_bfloat16 h1 = __float2bfloat16(v1);
                    const __nv_bfloat16 l0 = __float2bfloat16(v0 - __bfloat162float(h0));
                    const __nv_bfloat16 l1 = __float2bfloat16(v1 - __bfloat162float(h1));
                    const uint32_t hw = (uint32_t)__bfloat16_as_ushort(h0) |
                                        ((uint32_t)__bfloat16_as_ushort(h1) << 16);
                    const uint32_t lw = (uint32_t)__bfloat16_as_ushort(l0) |
                                        ((uint32_t)__bfloat16_as_ushort(l1) << 16);
                    const size_t rb = (((size_t)b * Hc + h) * Sc + s) * (3 * DHc);
                    if (EPI == 5) {
                        *reinterpret_cast<uint32_t*>(&outH[rb + d])           = hw;
                        *reinterpret_cast<uint32_t*>(&outH[rb + DHc + d])     = hw;
                        *reinterpret_cast<uint32_t*>(&outH[rb + 2 * DHc + d]) = lw;
                    } else {
                        *reinterpret_cast<uint32_t*>(&outH[rb + d])           = hw;
                        *reinterpret_cast<uint32_t*>(&outH[rb + DHc + d])     = lw;
                        *reinterpret_cast<uint32_t*>(&outH[rb + 2 * DHc + d]) = hw;
                    }
                }
            }
        }
    }
}

// ======================= split conversion kernels ===========================
template<int PATB>
__global__ void cvt_split(const float* __restrict__ src, __nv_bfloat16* __restrict__ dst, int K)
{
    const size_t i = (size_t)blockIdx.x * blockDim.x + threadIdx.x;
    const size_t rw = i / K, c = i % K;
    const float v = src[i];
    const __nv_bfloat16 hi = __float2bfloat16(v);
    const __nv_bfloat16 lo = __float2bfloat16(v - __bfloat162float(hi));
    __nv_bfloat16* row = dst + rw * (size_t)(3 * K);
    row[c]         = hi;
    row[K + c]     = PATB ? lo : hi;
    row[2 * K + c] = PATB ? hi : lo;
}

// ======================= SIMT attention kernels =============================
__global__ void softmax_stats_kernel(const float* __restrict__ sc,
                                     float* __restrict__ Mx, float* __restrict__ IZ)
{
    const int t = blockIdx.x * blockDim.x + threadIdx.x;
    const int z = blockIdx.y;
    const size_t base = (size_t)z * Sc * Sc;

    float m = -3.4e38f, sum = 0.f;
    for (int s = 0; s < Sc; ++s) {
        float x = sc[base + (size_t)s * Sc + t];
        if (x > m) { sum = sum * __expf(m - x) + 1.f; m = x; }
        else       { sum += __expf(x - m); }
    }
    Mx[(size_t)z * Sc + t] = m;
    IZ[(size_t)z * Sc + t] = 1.f / sum;
}

__global__ void __launch_bounds__(256)
gemm_av(const float* __restrict__ SCp, const float* __restrict__ VT,
        const float* __restrict__ Mx, const float* __restrict__ IZ,
        float* __restrict__ out)
{
    const int z = blockIdx.z;
    const float* A  = SCp + (size_t)z * Sc * Sc;
    const float* Bm = VT  + (size_t)z * DHc * Sc;
    const float* mz = Mx  + (size_t)z * Sc;
    const float* iz = IZ  + (size_t)z * Sc;

    __shared__ float As[2][BK][128];
    __shared__ float Bs[2][BK][64];

    const int tid = threadIdx.x;
    const int tx  = tid & 15;
    const int ty  = tid >> 4;
    const int m0  = blockIdx.y * 128;

    const int lr = tid >> 2;
    const int lc = (tid & 3) * 4;

    float acc[8][4];
    #pragma unroll
    for (int i = 0; i < 8; ++i)
        #pragma unroll
        for (int j = 0; j < 4; ++j) acc[i][j] = 0.f;

    const int nk = Sc / BK;

    auto loadA = [&](int k0, float4& o0, float4& o1) {
        const float4 mv = *reinterpret_cast<const float4*>(&mz[k0 + lc]);
        const float4 zv = *reinterpret_cast<const float4*>(&iz[k0 + lc]);
        float4 a0 = *reinterpret_cast<const float4*>(&A[(size_t)(m0 + lr)      * Sc + k0 + lc]);
        float4 a1 = *reinterpret_cast<const float4*>(&A[(size_t)(m0 + lr + 64) * Sc + k0 + lc]);
        o0.x = __expf(a0.x - mv.x) * zv.x; o0.y = __expf(a0.y - mv.y) * zv.y;
        o0.z = __expf(a0.z - mv.z) * zv.z; o0.w = __expf(a0.w - mv.w) * zv.w;
        o1.x = __expf(a1.x - mv.x) * zv.x; o1.y = __expf(a1.y - mv.y) * zv.y;
        o1.z = __expf(a1.z - mv.z) * zv.z; o1.w = __expf(a1.w - mv.w) * zv.w;
    };

    {
        float4 a0, a1;
        loadA(0, a0, a1);
        As[0][lc+0][lr] = a0.x; As[0][lc+1][lr] = a0.y; As[0][lc+2][lr] = a0.z; As[0][lc+3][lr] = a0.w;
        As[0][lc+0][lr+64] = a1.x; As[0][lc+1][lr+64] = a1.y; As[0][lc+2][lr+64] = a1.z; As[0][lc+3][lr+64] = a1.w;
        float4 b0 = *reinterpret_cast<const float4*>(&Bm[(size_t)lr * Sc + lc]);
        Bs[0][lc+0][lr] = b0.x; Bs[0][lc+1][lr] = b0.y; Bs[0][lc+2][lr] = b0.z; Bs[0][lc+3][lr] = b0.w;
    }
    __syncthreads();

    for (int kt = 0; kt < nk; ++kt) {
        const int cur = kt & 1, nxt = cur ^ 1;
        float4 pa0, pa1, pb0;
        const bool has_next = (kt + 1 < nk);
        if (has_next) {
            const int k0 = (kt + 1) * BK;
            loadA(k0, pa0, pa1);
            pb0 = *reinterpret_cast<const float4*>(&Bm[(size_t)lr * Sc + k0 + lc]);
        }

        #pragma unroll
        for (int k = 0; k < BK; ++k) {
            float ra[8], rb[4];
            const float4* a4 = reinterpret_cast<const float4*>(&As[cur][k][ty * 8]);
            float4 av0 = a4[0], av1 = a4[1];
            ra[0]=av0.x; ra[1]=av0.y; ra[2]=av0.z; ra[3]=av0.w;
            ra[4]=av1.x; ra[5]=av1.y; ra[6]=av1.z; ra[7]=av1.w;
            const float4 bv = reinterpret_cast<const float4*>(&Bs[cur][k][tx * 4])[0];
            rb[0]=bv.x; rb[1]=bv.y; rb[2]=bv.z; rb[3]=bv.w;
            #pragma unroll
            for (int i = 0; i < 8; ++i)
                #pragma unroll
                for (int j = 0; j < 4; ++j) acc[i][j] = fmaf(ra[i], rb[j], acc[i][j]);
        }

        if (has_next) {
            As[nxt][lc+0][lr] = pa0.x; As[nxt][lc+1][lr] = pa0.y; As[nxt][lc+2][lr] = pa0.z; As[nxt][lc+3][lr] = pa0.w;
            As[nxt][lc+0][lr+64] = pa1.x; As[nxt][lc+1][lr+64] = pa1.y; As[nxt][lc+2][lr+64] = pa1.z; As[nxt][lc+3][lr+64] = pa1.w;
            Bs[nxt][lc+0][lr] = pb0.x; Bs[nxt][lc+1][lr] = pb0.y; Bs[nxt][lc+2][lr] = pb0.z; Bs[nxt][lc+3][lr] = pb0.w;
            __syncthreads();
        }
    }

    const int b = z / Hc, h = z % Hc;
    #pragma unroll
    for (int i = 0; i < 8; ++i) {
        const int s = m0 + ty * 8 + i;
        const int d = tx * 4;
        float4 v = make_float4(acc[i][0], acc[i][1], acc[i][2], acc[i][3]);
        *reinterpret_cast<float4*>(&out[((size_t)b * Sc + s) * Dc + h * DHc + d]) = v;
    }
}

// LN + residual. SPLIT=0: fp32 out. SPLIT=1: (hi,hi,lo) bf16 triple out.
template<int SPLIT>
__global__ void ln_residual_kernel(const float* __restrict__ in,
                                   const float* __restrict__ gamma,
                                   const float* __restrict__ beta,
                                   float* __restrict__ out,
                                   __nv_bfloat16* __restrict__ outH)
{
    const size_t row = blockIdx.x;
    const float* xr = in + row * Dc;
    const int tid = threadIdx.x;

    const float v0 = xr[tid], v1 = xr[tid + 256], v2 = xr[tid + 512];

    __shared__ float red[256];
    red[tid] = v0 + v1 + v2;
    __syncthreads();
    #pragma unroll
    for (int o = 128; o > 0; o >>= 1) {
        if (tid < o) red[tid] += red[tid + o];
        __syncthreads();
    }
    const float mu = red[0] * (1.f / Dc);
    __syncthreads();

    const float d0 = v0 - mu, d1 = v1 - mu, d2 = v2 - mu;
    red[tid] = d0 * d0 + d1 * d1 + d2 * d2;
    __syncthreads();
    #pragma unroll
    for (int o = 128; o > 0; o >>= 1) {
        if (tid < o) red[tid] += red[tid + o];
        __syncthreads();
    }
    const float rstd = rsqrtf(red[0] * (1.f / Dc) + 1e-5f);

    const float o0 = d0 * rstd * gamma[tid]       + beta[tid]       + v0;
    const float o1 = d1 * rstd * gamma[tid + 256] + beta[tid + 256] + v1;
    const float o2 = d2 * rstd * gamma[tid + 512] + beta[tid + 512] + v2;

    if (SPLIT == 0) {
        float* orow = out + row * Dc;
        orow[tid] = o0; orow[tid + 256] = o1; orow[tid + 512] = o2;
    } else {
        __nv_bfloat16* orow = outH + row * (size_t)(3 * Dc);
        #pragma unroll
        for (int u = 0; u < 3; ++u) {
            const float v = (u == 0) ? o0 : (u == 1) ? o1 : o2;
            const int  c = tid + u * 256;
            const __nv_bfloat16 hi = __float2bfloat16(v);
            const __nv_bfloat16 lo = __float2bfloat16(v - __bfloat162float(hi));
            orow[c] = hi; orow[Dc + c] = hi; orow[2 * Dc + c] = lo;
        }
    }
}

// ---------------------------------------------------------------------------
extern "C" void kernel_launch(void* const* d_in, const int* in_sizes, int n_in,
                              void* d_out, int out_size)
{
    (void)in_sizes; (void)n_in; (void)out_size;
    const float* x    = (const float*)d_in[0];
    const int*   mask = (const int*)d_in[1];
    const float* Wq = (const float*)d_in[2];
    const float* bq = (const float*)d_in[3];
    const float* Wk = (const float*)d_in[4];
    const float* bk = (const float*)d_in[5];
    const float* Wv = (const float*)d_in[6];
    const float* bv = (const float*)d_in[7];
    const float* gamma = (const float*)d_in[8];
    const float* beta  = (const float*)d_in[9];
    const float* W1 = (const float*)d_in[10];
    const float* b1 = (const float*)d_in[11];
    const float* W2 = (const float*)d_in[12];
    const float* b2 = (const float*)d_in[13];
    float* out = (float*)d_out;

    float *vt, *sc, *mx, *izv, *a, *bb;
    cudaGetSymbolAddress((void**)&vt,  g_vt);
    cudaGetSymbolAddress((void**)&sc,  g_sc);
    cudaGetSymbolAddress((void**)&mx,  g_m);
    cudaGetSymbolAddress((void**)&izv, g_iz);
    cudaGetSymbolAddress((void**)&a,   g_a);
    cudaGetSymbolAddress((void**)&bb,  g_b);

    __nv_bfloat16 *xhl, *ahl, *hhl, *qs, *ks, *wqhl, *wkhl, *wvhl, *w1hl, *w2hl;
    cudaGetSymbolAddress((void**)&xhl,  g_xhl);
    cudaGetSymbolAddress((void**)&ahl,  g_ahl);
    cudaGetSymbolAddress((void**)&hhl,  g_hhl);
    cudaGetSymbolAddress((void**)&qs,   g_qs);
    cudaGetSymbolAddress((void**)&ks,   g_ks);
    cudaGetSymbolAddress((void**)&wqhl, g_wqhl);
    cudaGetSymbolAddress((void**)&wkhl, g_wkhl);
    cudaGetSymbolAddress((void**)&wvhl, g_wvhl);
    cudaGetSymbolAddress((void**)&w1hl, g_w1hl);
    cudaGetSymbolAddress((void**)&w2hl, g_w2hl);

    // raise dynamic smem limits (idempotent)
    cudaFuncSetAttribute(gemm_mma<0>, cudaFuncAttributeMaxDynamicSharedMemorySize, GEMM_SMEM);
    cudaFuncSetAttribute(gemm_mma<1>, cudaFuncAttributeMaxDynamicSharedMemorySize, GEMM_SMEM);
    cudaFuncSetAttribute(gemm_mma<3>, cudaFuncAttributeMaxDynamicSharedMemorySize, GEMM_SMEM);
    cudaFuncSetAttribute(gemm_mma<4>, cudaFuncAttributeMaxDynamicSharedMemorySize, GEMM_SMEM);
    cudaFuncSetAttribute(gemm_mma<5>, cudaFuncAttributeMaxDynamicSharedMemorySize, GEMM_SMEM);
    cudaFuncSetAttribute(gemm_mma<6>, cudaFuncAttributeMaxDynamicSharedMemorySize, GEMM_SMEM);

    const int MS = Bc * Sc;               // 8192
    const float scale = 1.0f / sqrtf((float)Sc);

    // 0) split conversions
    cvt_split<0><<<(MS * Ec) / 256, 256>>>(x,  xhl,  Ec);
    cvt_split<1><<<(Dc * Ec) / 256, 256>>>(Wq, wqhl, Ec);
    cvt_split<1><<<(Dc * Ec) / 256, 256>>>(Wk, wkhl, Ec);
    cvt_split<1><<<(Dc * Ec) / 256, 256>>>(Wv, wvhl, Ec);
    cvt_split<1><<<(Fc * Dc) / 256, 256>>>(W1, w1hl, Dc);
    cvt_split<1><<<(Dc * Fc) / 256, 256>>>(W2, w2hl, Fc);

    // 1) QKV projections (tensor cores); q/k written as split triples
    {
        dim3 grid(Dc / 128, MS / 128);
        gemm_mma<5><<<grid, 256, GEMM_SMEM>>>(xhl, wqhl, Dc, 3 * Ec, 0, 0, bq, nullptr, 0.f, nullptr, qs);
        gemm_mma<6><<<grid, 256, GEMM_SMEM>>>(xhl, wkhl, Dc, 3 * Ec, 0, 0, bk, nullptr, 0.f, nullptr, ks);
        gemm_mma<3><<<grid, 256, GEMM_SMEM>>>(xhl, wvhl, Dc, 3 * Ec, 0, 0, bv, nullptr, 0.f, vt, nullptr);
    }

    // 2) scores = q @ k^T / sqrt(S), mask -> -1000 (tensor cores, batched)
    {
        dim3 grid(Sc / 128, Sc / 128, Bc * Hc);
        gemm_mma<4><<<grid, 256, GEMM_SMEM>>>(qs, ks, Sc, 3 * DHc,
                                              (long)Sc * 3 * DHc, (long)Sc * 3 * DHc,
                                              nullptr, mask, scale, sc, nullptr);
    }

    // 3) column-softmax stats
    {
        dim3 grid(Sc / 256, Bc * Hc);
        softmax_stats_kernel<<<grid, 256>>>(sc, mx, izv);
    }

    // 4) o = softmax(sc) @ v -> concat heads
    {
        dim3 grid(1, Sc / 128, Bc * Hc);
        gemm_av<<<grid, 256>>>(sc, vt, mx, izv, a);
    }

    // 5) a = LN(a) + a  -> split bf16 triple
    ln_residual_kernel<1><<<MS, 256>>>(a, gamma, beta, nullptr, ahl);

    // 6) h = relu(a @ W1^T + b1) -> split triple
    {
        dim3 grid(Fc / 128, MS / 128);
        gemm_mma<1><<<grid, 256, GEMM_SMEM>>>(ahl, w1hl, Fc, 3 * Dc, 0, 0, b1, nullptr, 0.f, nullptr, hhl);
    }

    // 7) bb = h @ W2^T + b2
    {
        dim3 grid(Dc / 128, MS / 128);
        gemm_mma<0><<<grid, 256, GEMM_SMEM>>>(hhl, w2hl, Dc, 3 * Fc, 0, 0, b2, nullptr, 0.f, bb, nullptr);
    }

    // 8) out = LN(bb) + bb
    ln_residual_kernel<0><<<MS, 256>>>(bb, gamma, beta, out, nullptr);
}

// round 8
// speedup vs baseline: 2.2372x; 1.1569x over previous
#include <cuda_runtime.h>
#include <cuda_bf16.h>
#include <math.h>
#include <stdint.h>

// Problem dims (fixed by the reference)
#define Bc  4
#define Sc  2048
#define Ec  768
#define Dc  768
#define Hc  12
#define DHc 64
#define Fc  3072

#define LDSH 40                      // bf16 per smem row (80 B pitch)
#define STAGE_BYTES (128 * LDSH * 2) // one matrix, one stage = 10240 B
#define GEMM_SMEM (3 * 2 * STAGE_BYTES)

// ---------------- scratch (device globals: allocation-free) ----------------
__device__ float g_vt[(size_t)Bc*Hc*DHc*Sc];   // [B,H,dh,S]
__device__ float g_sc[(size_t)Bc*Hc*Sc*Sc];    // [B,H,S,S] masked scores
__device__ float g_m [(size_t)Bc*Hc*Sc];
__device__ float g_iz[(size_t)Bc*Hc*Sc];
__device__ float g_a [(size_t)Bc*Sc*Dc];
__device__ float g_b [(size_t)Bc*Sc*Dc];

// split-bf16 buffers (A pattern = hi,hi,lo ; B pattern = hi,lo,hi)
__device__ __nv_bfloat16 g_xhl [(size_t)Bc*Sc*3*Ec];
__device__ __nv_bfloat16 g_ahl [(size_t)Bc*Sc*3*Dc];
__device__ __nv_bfloat16 g_hhl [(size_t)Bc*Sc*3*Fc];
__device__ __nv_bfloat16 g_qs  [(size_t)Bc*Hc*Sc*3*DHc];  // q split (A pat)
__device__ __nv_bfloat16 g_ks  [(size_t)Bc*Hc*Sc*3*DHc];  // k split (B pat)
__device__ __nv_bfloat16 g_wqhl[(size_t)Dc*3*Ec];
__device__ __nv_bfloat16 g_wkhl[(size_t)Dc*3*Ec];
__device__ __nv_bfloat16 g_wvhl[(size_t)Dc*3*Ec];
__device__ __nv_bfloat16 g_w1hl[(size_t)Fc*3*Dc];
__device__ __nv_bfloat16 g_w2hl[(size_t)Dc*3*Fc];

// ======================= warp-MMA helpers ===================================
__device__ __forceinline__ uint32_t smem_u32(const void* p) {
    uint32_t a;
    asm("{ .reg .u64 t; cvta.to.shared.u64 t, %1; cvt.u32.u64 %0, t; }" : "=r"(a) : "l"(p));
    return a;
}
__device__ __forceinline__ void ldsm_x4(uint32_t& r0, uint32_t& r1, uint32_t& r2, uint32_t& r3,
                                        uint32_t addr) {
    asm volatile("ldmatrix.sync.aligned.m8n8.x4.shared.b16 {%0,%1,%2,%3}, [%4];"
                 : "=r"(r0), "=r"(r1), "=r"(r2), "=r"(r3) : "r"(addr));
}
__device__ __forceinline__ void mma16816(float* d, const uint32_t* a, uint32_t b0, uint32_t b1) {
    asm volatile("mma.sync.aligned.m16n8k16.row.col.f32.bf16.bf16.f32 "
                 "{%0,%1,%2,%3}, {%4,%5,%6,%7}, {%8,%9}, {%0,%1,%2,%3};"
                 : "+f"(d[0]), "+f"(d[1]), "+f"(d[2]), "+f"(d[3])
                 : "r"(a[0]), "r"(a[1]), "r"(a[2]), "r"(a[3]), "r"(b0), "r"(b1));
}
#define CP_ASYNC16(dst, src) \
    asm volatile("cp.async.cg.shared.global [%0], [%1], 16;" :: "r"(dst), "l"(src))
#define CP_COMMIT() asm volatile("cp.async.commit_group;")
#define CP_WAIT1()  asm volatile("cp.async.wait_group 1;")

__device__ __forceinline__ uint32_t pack_bf16x2(float a, float b) {
    const __nv_bfloat16 ha = __float2bfloat16(a);
    const __nv_bfloat16 hb = __float2bfloat16(b);
    return (uint32_t)__bfloat16_as_ushort(ha) | ((uint32_t)__bfloat16_as_ushort(hb) << 16);
}

// ======================= split-bf16 NT GEMM via mma.sync ====================
// (unchanged from R7 — proven)
template<int EPI>
__global__ void __launch_bounds__(256, 2)
gemm_mma(const __nv_bfloat16* __restrict__ A, const __nv_bfloat16* __restrict__ Bw,
         int N, int Kp, long strideA, long strideB,
         const float* __restrict__ bias, const int* __restrict__ mask, float scale,
         float* __restrict__ outF, __nv_bfloat16* __restrict__ outH)
{
    extern __shared__ char dynsm[];

    const int z = blockIdx.z;
    A  += (size_t)z * strideA;
    Bw += (size_t)z * strideB;

    const int tid  = threadIdx.x;
    const int wid  = tid >> 5;
    const int lane = tid & 31;
    const int m0   = blockIdx.y * 128;
    const int n0   = blockIdx.x * 128;
    const int wm   = (wid & 1) * 64;
    const int wn   = (wid >> 1) * 32;

    const uint32_t smBase = smem_u32(dynsm);

    float acc[4][4][4];
    #pragma unroll
    for (int i = 0; i < 4; ++i)
        #pragma unroll
        for (int j = 0; j < 4; ++j)
            #pragma unroll
            for (int p = 0; p < 4; ++p) acc[i][j][p] = 0.f;

    const int nk = Kp / 32;

    auto stage = [&](int s, int kt) {
        const int kc = kt * 32;
        const uint32_t base = smBase + s * (2 * STAGE_BYTES);
        #pragma unroll
        for (int i = 0; i < 2; ++i) {
            const int id = tid + i * 256;
            const int r  = id >> 2;
            const int c  = (id & 3) * 8;
            const uint32_t dA = base + (uint32_t)(r * 80 + c * 2);
            const uint32_t dB = dA + STAGE_BYTES;
            CP_ASYNC16(dA, &A [(size_t)(m0 + r) * Kp + kc + c]);
            CP_ASYNC16(dB, &Bw[(size_t)(n0 + r) * Kp + kc + c]);
        }
    };

    stage(0, 0); CP_COMMIT();
    stage(1, 1); CP_COMMIT();

    const int lrow = lane & 15;
    const int lcol = (lane >> 4) * 8;

    for (int kt = 0; kt < nk; ++kt) {
        CP_WAIT1();
        __syncthreads();

        const uint32_t aBase = smBase + (kt % 3) * (2 * STAGE_BYTES);
        const uint32_t bBase = aBase + STAGE_BYTES;

        #pragma unroll
        for (int ks = 0; ks < 32; ks += 16) {
            uint32_t a[4][4];
            #pragma unroll
            for (int mi = 0; mi < 4; ++mi) {
                const uint32_t ad = aBase + (uint32_t)(wm + mi * 16 + lrow) * 80
                                          + (uint32_t)(ks + lcol) * 2;
                ldsm_x4(a[mi][0], a[mi][1], a[mi][2], a[mi][3], ad);
            }
            uint32_t b[2][4];
            #pragma unroll
            for (int bj = 0; bj < 2; ++bj) {
                const uint32_t bd = bBase + (uint32_t)(wn + bj * 16 + lrow) * 80
                                          + (uint32_t)(ks + lcol) * 2;
                ldsm_x4(b[bj][0], b[bj][1], b[bj][2], b[bj][3], bd);
            }
            #pragma unroll
            for (int mi = 0; mi < 4; ++mi)
                #pragma unroll
                for (int nj = 0; nj < 4; ++nj)
                    mma16816(acc[mi][nj], a[mi], b[nj >> 1][nj & 1], b[nj >> 1][(nj & 1) + 2]);
        }

        if (kt + 2 < nk) stage((kt + 2) % 3, kt + 2);
        CP_COMMIT();
    }

    // ---------------- epilogue ----------------
    const int r4 = lane >> 2;
    const int c2 = (lane & 3) * 2;

    #pragma unroll
    for (int mi = 0; mi < 4; ++mi) {
        #pragma unroll
        for (int half = 0; half < 2; ++half) {
            const int m = m0 + wm + mi * 16 + r4 + half * 8;
            #pragma unroll
            for (int nj = 0; nj < 4; ++nj) {
                const int n = n0 + wn + nj * 8 + c2;
                float v0 = acc[mi][nj][half * 2];
                float v1 = acc[mi][nj][half * 2 + 1];
                if (EPI != 4) { v0 += bias[n]; v1 += bias[n + 1]; }
                if (EPI == 0) {
                    *reinterpret_cast<float2*>(&outF[(size_t)m * N + n]) = make_float2(v0, v1);
                } else if (EPI == 1) {
                    const float u0 = fmaxf(v0, 0.f), u1 = fmaxf(v1, 0.f);
                    const __nv_bfloat16 h0 = __float2bfloat16(u0);
                    const __nv_bfloat16 h1 = __float2bfloat16(u1);
                    const uint32_t hw = (uint32_t)__bfloat16_as_ushort(h0) |
                                        ((uint32_t)__bfloat16_as_ushort(h1) << 16);
                    const uint32_t lw = pack_bf16x2(u0 - __bfloat162float(h0),
                                                    u1 - __bfloat162float(h1));
                    const size_t rb = (size_t)m * (3 * N);
                    *reinterpret_cast<uint32_t*>(&outH[rb + n])         = hw;
                    *reinterpret_cast<uint32_t*>(&outH[rb + N + n])     = hw;
                    *reinterpret_cast<uint32_t*>(&outH[rb + 2 * N + n]) = lw;
                } else if (EPI == 3) {
                    const int b = m >> 11, s = m & 2047;
                    const int h = n >> 6,  d = n & 63;
                    outF[(((size_t)b * Hc + h) * DHc + d)     * Sc + s] = v0;
                    outF[(((size_t)b * Hc + h) * DHc + d + 1) * Sc + s] = v1;
                } else if (EPI == 4) {
                    const int bq = z / Hc;
                    const int2 mk = *reinterpret_cast<const int2*>(
                        &mask[((size_t)bq * Sc + m) * Sc + n]);
                    float2 v;
                    v.x = mk.x ? -1000.f : v0 * scale;
                    v.y = mk.y ? -1000.f : v1 * scale;
                    *reinterpret_cast<float2*>(&outF[((size_t)z * Sc + m) * Sc + n]) = v;
                } else { // EPI 5 / 6
                    const int b = m >> 11, s = m & 2047;
                    const int h = n >> 6,  d = n & 63;
                    const __nv_bfloat16 h0 = __float2bfloat16(v0);
                    const __nv_bfloat16 h1 = __float2bfloat16(v1);
                    const uint32_t hw = (uint32_t)__bfloat16_as_ushort(h0) |
                                        ((uint32_t)__bfloat16_as_ushort(h1) << 16);
                    const uint32_t lw = pack_bf16x2(v0 - __bfloat162float(h0),
                                                    v1 - __bfloat162float(h1));
                    const size_t rb = (((size_t)b * Hc + h) * Sc + s) * (3 * DHc);
                    if (EPI == 5) {
                        *reinterpret_cast<uint32_t*>(&outH[rb + d])           = hw;
                        *reinterpret_cast<uint32_t*>(&outH[rb + DHc + d])     = hw;
                        *reinterpret_cast<uint32_t*>(&outH[rb + 2 * DHc + d]) = lw;
                    } else {
                        *reinterpret_cast<uint32_t*>(&outH[rb + d])           = hw;
                        *reinterpret_cast<uint32_t*>(&outH[rb + DHc + d])     = lw;
                        *reinterpret_cast<uint32_t*>(&outH[rb + 2 * DHc + d]) = hw;
                    }
                }
            }
        }
    }
}

// ======================= attn@V via mma.sync ================================
// o[b, s, h*64+d] = sum_t p(s,t) v(d,t),  p = exp(sc - m_t) * iz_t.
// Per 16-t chunk: load sc/vt fp32, convert, 3-term split into smem
// (A = p_hi,p_hi,p_lo ; B = v_hi,v_lo,v_hi -> k-chunk 48), ldmatrix + mma.
// Tile M=128 (s) x N=64 (d). 8 warps: 2M x 4N, warp tile 64x16.
#define AVP 56   // smem pitch in bf16 (112 B, odd multiple of 16 B)

__global__ void __launch_bounds__(256, 2)
gemm_av_mma(const float* __restrict__ SCp, const float* __restrict__ VT,
            const float* __restrict__ Mx, const float* __restrict__ IZ,
            float* __restrict__ out)
{
    __shared__ __nv_bfloat16 sA[2][128 * AVP];
    __shared__ __nv_bfloat16 sB[2][64 * AVP];

    const int z = blockIdx.z;
    const float* A  = SCp + (size_t)z * Sc * Sc;
    const float* Bm = VT  + (size_t)z * DHc * Sc;
    const float* mz = Mx  + (size_t)z * Sc;
    const float* iz = IZ  + (size_t)z * Sc;

    const int tid  = threadIdx.x;
    const int wid  = tid >> 5;
    const int lane = tid & 31;
    const int m0   = blockIdx.y * 128;
    const int wm   = (wid & 1) * 64;
    const int wn   = (wid >> 1) * 16;

    const uint32_t sAu = smem_u32(sA);
    const uint32_t sBu = smem_u32(sB);

    float acc[4][2][4];
    #pragma unroll
    for (int i = 0; i < 4; ++i)
        #pragma unroll
        for (int j = 0; j < 2; ++j)
            #pragma unroll
            for (int p = 0; p < 4; ++p) acc[i][j][p] = 0.f;

    const int r  = tid >> 2;          // 0..63
    const int j4 = (tid & 3) * 4;     // 0,4,8,12

    float4 ra0, ra1, rb, pm, pz;
    auto fetch = [&](int kt) {
        const int t0 = kt * 16 + j4;
        pm  = *reinterpret_cast<const float4*>(&mz[t0]);
        pz  = *reinterpret_cast<const float4*>(&iz[t0]);
        ra0 = *reinterpret_cast<const float4*>(&A[(size_t)(m0 + r)      * Sc + t0]);
        ra1 = *reinterpret_cast<const float4*>(&A[(size_t)(m0 + r + 64) * Sc + t0]);
        rb  = *reinterpret_cast<const float4*>(&Bm[(size_t)r * Sc + t0]);
    };

    auto cvst = [&](int buf) {
        // probabilities for the two A rows
        float p0[4] = { __expf(ra0.x - pm.x) * pz.x, __expf(ra0.y - pm.y) * pz.y,
                        __expf(ra0.z - pm.z) * pz.z, __expf(ra0.w - pm.w) * pz.w };
        float p1[4] = { __expf(ra1.x - pm.x) * pz.x, __expf(ra1.y - pm.y) * pz.y,
                        __expf(ra1.z - pm.z) * pz.z, __expf(ra1.w - pm.w) * pz.w };
        float vb[4] = { rb.x, rb.y, rb.z, rb.w };

        uint32_t h0[2], l0[2], h1[2], l1[2], hb[2], lb[2];
        #pragma unroll
        for (int p = 0; p < 2; ++p) {
            const float a0 = p0[2*p], a1 = p0[2*p+1];
            const __nv_bfloat16 ha0 = __float2bfloat16(a0), ha1 = __float2bfloat16(a1);
            h0[p] = (uint32_t)__bfloat16_as_ushort(ha0) | ((uint32_t)__bfloat16_as_ushort(ha1) << 16);
            l0[p] = pack_bf16x2(a0 - __bfloat162float(ha0), a1 - __bfloat162float(ha1));
            const float b0 = p1[2*p], b1 = p1[2*p+1];
            const __nv_bfloat16 hb0 = __float2bfloat16(b0), hb1 = __float2bfloat16(b1);
            h1[p] = (uint32_t)__bfloat16_as_ushort(hb0) | ((uint32_t)__bfloat16_as_ushort(hb1) << 16);
            l1[p] = pack_bf16x2(b0 - __bfloat162float(hb0), b1 - __bfloat162float(hb1));
            const float c0 = vb[2*p], c1 = vb[2*p+1];
            const __nv_bfloat16 hc0 = __float2bfloat16(c0), hc1 = __float2bfloat16(c1);
            hb[p] = (uint32_t)__bfloat16_as_ushort(hc0) | ((uint32_t)__bfloat16_as_ushort(hc1) << 16);
            lb[p] = pack_bf16x2(c0 - __bfloat162float(hc0), c1 - __bfloat162float(hc1));
        }
        // A rows r and r+64: (hi @ j, hi @ 16+j, lo @ 32+j)
        __nv_bfloat16* a0p = &sA[buf][(size_t)r * AVP];
        __nv_bfloat16* a1p = &sA[buf][(size_t)(r + 64) * AVP];
        *reinterpret_cast<uint2*>(&a0p[j4])      = make_uint2(h0[0], h0[1]);
        *reinterpret_cast<uint2*>(&a0p[16 + j4]) = make_uint2(h0[0], h0[1]);
        *reinterpret_cast<uint2*>(&a0p[32 + j4]) = make_uint2(l0[0], l0[1]);
        *reinterpret_cast<uint2*>(&a1p[j4])      = make_uint2(h1[0], h1[1]);
        *reinterpret_cast<uint2*>(&a1p[16 + j4]) = make_uint2(h1[0], h1[1]);
        *reinterpret_cast<uint2*>(&a1p[32 + j4]) = make_uint2(l1[0], l1[1]);
        // B row r (d): (hi @ j, lo @ 16+j, hi @ 32+j)
        __nv_bfloat16* bp = &sB[buf][(size_t)r * AVP];
        *reinterpret_cast<uint2*>(&bp[j4])      = make_uint2(hb[0], hb[1]);
        *reinterpret_cast<uint2*>(&bp[16 + j4]) = make_uint2(lb[0], lb[1]);
        *reinterpret_cast<uint2*>(&bp[32 + j4]) = make_uint2(hb[0], hb[1]);
    };

    fetch(0);

    const int lrow = lane & 15;
    const int lcol = (lane >> 4) * 8;
    const int nk = Sc / 16;   // 128

    for (int kt = 0; kt < nk; ++kt) {
        const int buf = kt & 1;
        cvst(buf);
        __syncthreads();
        if (kt + 1 < nk) fetch(kt + 1);

        const uint32_t aBase = sAu + buf * (128 * AVP * 2);
        const uint32_t bBase = sBu + buf * (64 * AVP * 2);

        #pragma unroll
        for (int ks = 0; ks < 48; ks += 16) {
            uint32_t a[4][4];
            #pragma unroll
            for (int mi = 0; mi < 4; ++mi) {
                const uint32_t ad = aBase + (uint32_t)(wm + mi * 16 + lrow) * (AVP * 2)
                                          + (uint32_t)(ks + lcol) * 2;
                ldsm_x4(a[mi][0], a[mi][1], a[mi][2], a[mi][3], ad);
            }
            uint32_t b[4];
            const uint32_t bd = bBase + (uint32_t)(wn + lrow) * (AVP * 2)
                                      + (uint32_t)(ks + lcol) * 2;
            ldsm_x4(b[0], b[1], b[2], b[3], bd);
            #pragma unroll
            for (int mi = 0; mi < 4; ++mi)
                #pragma unroll
                for (int nj = 0; nj < 2; ++nj)
                    mma16816(acc[mi][nj], a[mi], b[nj], b[nj + 2]);
        }
        __syncthreads();
    }

    // epilogue: out[b, s, h*64 + d]
    const int b = z / Hc, h = z % Hc;
    const int r4 = lane >> 2;
    const int c2 = (lane & 3) * 2;
    #pragma unroll
    for (int mi = 0; mi < 4; ++mi) {
        #pragma unroll
        for (int half = 0; half < 2; ++half) {
            const int s = m0 + wm + mi * 16 + r4 + half * 8;
            #pragma unroll
            for (int nj = 0; nj < 2; ++nj) {
                const int d = wn + nj * 8 + c2;
                float2 v = make_float2(acc[mi][nj][half * 2], acc[mi][nj][half * 2 + 1]);
                *reinterpret_cast<float2*>(&out[((size_t)b * Sc + s) * Dc + h * DHc + d]) = v;
            }
        }
    }
}

// ======================= split conversion kernels ===========================
template<int PATB>
__global__ void cvt_split(const float* __restrict__ src, __nv_bfloat16* __restrict__ dst, int K)
{
    const size_t i = (size_t)blockIdx.x * blockDim.x + threadIdx.x;
    const size_t rw = i / K, c = i % K;
    const float v = src[i];
    const __nv_bfloat16 hi = __float2bfloat16(v);
    const __nv_bfloat16 lo = __float2bfloat16(v - __bfloat162float(hi));
    __nv_bfloat16* row = dst + rw * (size_t)(3 * K);
    row[c]         = hi;
    row[K + c]     = PATB ? lo : hi;
    row[2 * K + c] = PATB ? hi : lo;
}

// ======================= SIMT kernels =======================================
__global__ void softmax_stats_kernel(const float* __restrict__ sc,
                                     float* __restrict__ Mx, float* __restrict__ IZ)
{
    const int t = blockIdx.x * blockDim.x + threadIdx.x;
    const int z = blockIdx.y;
    const size_t base = (size_t)z * Sc * Sc;

    float m = -3.4e38f, sum = 0.f;
    for (int s = 0; s < Sc; ++s) {
        float x = sc[base + (size_t)s * Sc + t];
        if (x > m) { sum = sum * __expf(m - x) + 1.f; m = x; }
        else       { sum += __expf(x - m); }
    }
    Mx[(size_t)z * Sc + t] = m;
    IZ[(size_t)z * Sc + t] = 1.f / sum;
}

// LN + residual. SPLIT=0: fp32 out. SPLIT=1: (hi,hi,lo) bf16 triple out.
template<int SPLIT>
__global__ void ln_residual_kernel(const float* __restrict__ in,
                                   const float* __restrict__ gamma,
                                   const float* __restrict__ beta,
                                   float* __restrict__ out,
                                   __nv_bfloat16* __restrict__ outH)
{
    const size_t row = blockIdx.x;
    const float* xr = in + row * Dc;
    const int tid = threadIdx.x;

    const float v0 = xr[tid], v1 = xr[tid + 256], v2 = xr[tid + 512];

    __shared__ float red[256];
    red[tid] = v0 + v1 + v2;
    __syncthreads();
    #pragma unroll
    for (int o = 128; o > 0; o >>= 1) {
        if (tid < o) red[tid] += red[tid + o];
        __syncthreads();
    }
    const float mu = red[0] * (1.f / Dc);
    __syncthreads();

    const float d0 = v0 - mu, d1 = v1 - mu, d2 = v2 - mu;
    red[tid] = d0 * d0 + d1 * d1 + d2 * d2;
    __syncthreads();
    #pragma unroll
    for (int o = 128; o > 0; o >>= 1) {
        if (tid < o) red[tid] += red[tid + o];
        __syncthreads();
    }
    const float rstd = rsqrtf(red[0] * (1.f / Dc) + 1e-5f);

    const float o0 = d0 * rstd * gamma[tid]       + beta[tid]       + v0;
    const float o1 = d1 * rstd * gamma[tid + 256] + beta[tid + 256] + v1;
    const float o2 = d2 * rstd * gamma[tid + 512] + beta[tid + 512] + v2;

    if (SPLIT == 0) {
        float* orow = out + row * Dc;
        orow[tid] = o0; orow[tid + 256] = o1; orow[tid + 512] = o2;
    } else {
        __nv_bfloat16* orow = outH + row * (size_t)(3 * Dc);
        #pragma unroll
        for (int u = 0; u < 3; ++u) {
            const float v = (u == 0) ? o0 : (u == 1) ? o1 : o2;
            const int  c = tid + u * 256;
            const __nv_bfloat16 hi = __float2bfloat16(v);
            const __nv_bfloat16 lo = __float2bfloat16(v - __bfloat162float(hi));
            orow[c] = hi; orow[Dc + c] = hi; orow[2 * Dc + c] = lo;
        }
    }
}

// ---------------------------------------------------------------------------
extern "C" void kernel_launch(void* const* d_in, const int* in_sizes, int n_in,
                              void* d_out, int out_size)
{
    (void)in_sizes; (void)n_in; (void)out_size;
    const float* x    = (const float*)d_in[0];
    const int*   mask = (const int*)d_in[1];
    const float* Wq = (const float*)d_in[2];
    const float* bq = (const float*)d_in[3];
    const float* Wk = (const float*)d_in[4];
    const float* bk = (const float*)d_in[5];
    const float* Wv = (const float*)d_in[6];
    const float* bv = (const float*)d_in[7];
    const float* gamma = (const float*)d_in[8];
    const float* beta  = (const float*)d_in[9];
    const float* W1 = (const float*)d_in[10];
    const float* b1 = (const float*)d_in[11];
    const float* W2 = (const float*)d_in[12];
    const float* b2 = (const float*)d_in[13];
    float* out = (float*)d_out;

    float *vt, *sc, *mx, *izv, *a, *bb;
    cudaGetSymbolAddress((void**)&vt,  g_vt);
    cudaGetSymbolAddress((void**)&sc,  g_sc);
    cudaGetSymbolAddress((void**)&mx,  g_m);
    cudaGetSymbolAddress((void**)&izv, g_iz);
    cudaGetSymbolAddress((void**)&a,   g_a);
    cudaGetSymbolAddress((void**)&bb,  g_b);

    __nv_bfloat16 *xhl, *ahl, *hhl, *qs, *ks, *wqhl, *wkhl, *wvhl, *w1hl, *w2hl;
    cudaGetSymbolAddress((void**)&xhl,  g_xhl);
    cudaGetSymbolAddress((void**)&ahl,  g_ahl);
    cudaGetSymbolAddress((void**)&hhl,  g_hhl);
    cudaGetSymbolAddress((void**)&qs,   g_qs);
    cudaGetSymbolAddress((void**)&ks,   g_ks);
    cudaGetSymbolAddress((void**)&wqhl, g_wqhl);
    cudaGetSymbolAddress((void**)&wkhl, g_wkhl);
    cudaGetSymbolAddress((void**)&wvhl, g_wvhl);
    cudaGetSymbolAddress((void**)&w1hl, g_w1hl);
    cudaGetSymbolAddress((void**)&w2hl, g_w2hl);

    cudaFuncSetAttribute(gemm_mma<0>, cudaFuncAttributeMaxDynamicSharedMemorySize, GEMM_SMEM);
    cudaFuncSetAttribute(gemm_mma<1>, cudaFuncAttributeMaxDynamicSharedMemorySize, GEMM_SMEM);
    cudaFuncSetAttribute(gemm_mma<3>, cudaFuncAttributeMaxDynamicSharedMemorySize, GEMM_SMEM);
    cudaFuncSetAttribute(gemm_mma<4>, cudaFuncAttributeMaxDynamicSharedMemorySize, GEMM_SMEM);
    cudaFuncSetAttribute(gemm_mma<5>, cudaFuncAttributeMaxDynamicSharedMemorySize, GEMM_SMEM);
    cudaFuncSetAttribute(gemm_mma<6>, cudaFuncAttributeMaxDynamicSharedMemorySize, GEMM_SMEM);

    const int MS = Bc * Sc;               // 8192
    const float scale = 1.0f / sqrtf((float)Sc);

    // 0) split conversions
    cvt_split<0><<<(MS * Ec) / 256, 256>>>(x,  xhl,  Ec);
    cvt_split<1><<<(Dc * Ec) / 256, 256>>>(Wq, wqhl, Ec);
    cvt_split<1><<<(Dc * Ec) / 256, 256>>>(Wk, wkhl, Ec);
    cvt_split<1><<<(Dc * Ec) / 256, 256>>>(Wv, wvhl, Ec);
    cvt_split<1><<<(Fc * Dc) / 256, 256>>>(W1, w1hl, Dc);
    cvt_split<1><<<(Dc * Fc) / 256, 256>>>(W2, w2hl, Fc);

    // 1) QKV projections (tensor cores); q/k written as split triples
    {
        dim3 grid(Dc / 128, MS / 128);
        gemm_mma<5><<<grid, 256, GEMM_SMEM>>>(xhl, wqhl, Dc, 3 * Ec, 0, 0, bq, nullptr, 0.f, nullptr, qs);
        gemm_mma<6><<<grid, 256, GEMM_SMEM>>>(xhl, wkhl, Dc, 3 * Ec, 0, 0, bk, nullptr, 0.f, nullptr, ks);
        gemm_mma<3><<<grid, 256, GEMM_SMEM>>>(xhl, wvhl, Dc, 3 * Ec, 0, 0, bv, nullptr, 0.f, vt, nullptr);
    }

    // 2) scores = q @ k^T / sqrt(S), mask -> -1000 (tensor cores, batched)
    {
        dim3 grid(Sc / 128, Sc / 128, Bc * Hc);
        gemm_mma<4><<<grid, 256, GEMM_SMEM>>>(qs, ks, Sc, 3 * DHc,
                                              (long)Sc * 3 * DHc, (long)Sc * 3 * DHc,
                                              nullptr, mask, scale, sc, nullptr);
    }

    // 3) column-softmax stats
    {
        dim3 grid(Sc / 256, Bc * Hc);
        softmax_stats_kernel<<<grid, 256>>>(sc, mx, izv);
    }

    // 4) o = softmax(sc) @ v -> concat heads (tensor cores, fused exp/split)
    {
        dim3 grid(1, Sc / 128, Bc * Hc);
        gemm_av_mma<<<grid, 256>>>(sc, vt, mx, izv, a);
    }

    // 5) a = LN(a) + a  -> split bf16 triple
    ln_residual_kernel<1><<<MS, 256>>>(a, gamma, beta, nullptr, ahl);

    // 6) h = relu(a @ W1^T + b1) -> split triple
    {
        dim3 grid(Fc / 128, MS / 128);
        gemm_mma<1><<<grid, 256, GEMM_SMEM>>>(ahl, w1hl, Fc, 3 * Dc, 0, 0, b1, nullptr, 0.f, nullptr, hhl);
    }

    // 7) bb = h @ W2^T + b2
    {
        dim3 grid(Dc / 128, MS / 128);
        gemm_mma<0><<<grid, 256, GEMM_SMEM>>>(hhl, w2hl, Dc, 3 * Fc, 0, 0, b2, nullptr, 0.f, bb, nullptr);
    }

    // 8) out = LN(bb) + bb
    ln_residual_kernel<0><<<MS, 256>>>(bb, gamma, beta, out, nullptr);
}

// round 9
// speedup vs baseline: 2.9702x; 1.3276x over previous
#include <cuda_runtime.h>
#include <cuda_bf16.h>
#include <cuda_fp16.h>
#include <math.h>
#include <stdint.h>

// Problem dims (fixed by the reference)
#define Bc  4
#define Sc  2048
#define Ec  768
#define Dc  768
#define Hc  12
#define DHc 64
#define Fc  3072

#define LDSH 40                      // bf16 per smem row (80 B pitch)
#define STAGE_BYTES (128 * LDSH * 2) // one matrix, one stage = 10240 B
#define GEMM_SMEM (3 * 2 * STAGE_BYTES)

// ---------------- scratch (device globals: allocation-free) ----------------
__device__ float    g_vt[(size_t)Bc*Hc*DHc*Sc];       // [B,H,dh,S] fp32
__device__ __half   g_ph[(size_t)Bc*Hc*Sc*Sc];        // p = exp(masked score) fp16 (403 MB)
__device__ __half   g_vh[(size_t)Bc*Hc*DHc*Sc];       // v / colsum, fp16
__device__ float    g_csp[(size_t)Bc*Hc*16*Sc];       // per-mtile column partial sums
__device__ float    g_colsum[(size_t)Bc*Hc*Sc];
__device__ uint32_t g_mb[(size_t)Bc*Sc*(Sc/32)];      // bit-packed mask
__device__ float    g_a [(size_t)Bc*Sc*Dc];
__device__ float    g_b [(size_t)Bc*Sc*Dc];

// split-bf16 buffers (A pattern = hi,hi,lo ; B pattern = hi,lo,hi)
__device__ __nv_bfloat16 g_xhl [(size_t)Bc*Sc*3*Ec];
__device__ __nv_bfloat16 g_ahl [(size_t)Bc*Sc*3*Dc];
__device__ __nv_bfloat16 g_hhl [(size_t)Bc*Sc*3*Fc];
__device__ __nv_bfloat16 g_qs  [(size_t)Bc*Hc*Sc*3*DHc];
__device__ __nv_bfloat16 g_ks  [(size_t)Bc*Hc*Sc*3*DHc];
__device__ __nv_bfloat16 g_wqhl[(size_t)Dc*3*Ec];
__device__ __nv_bfloat16 g_wkhl[(size_t)Dc*3*Ec];
__device__ __nv_bfloat16 g_wvhl[(size_t)Dc*3*Ec];
__device__ __nv_bfloat16 g_w1hl[(size_t)Fc*3*Dc];
__device__ __nv_bfloat16 g_w2hl[(size_t)Dc*3*Fc];

// ======================= warp-MMA helpers ===================================
__device__ __forceinline__ uint32_t smem_u32(const void* p) {
    uint32_t a;
    asm("{ .reg .u64 t; cvta.to.shared.u64 t, %1; cvt.u32.u64 %0, t; }" : "=r"(a) : "l"(p));
    return a;
}
__device__ __forceinline__ void ldsm_x4(uint32_t& r0, uint32_t& r1, uint32_t& r2, uint32_t& r3,
                                        uint32_t addr) {
    asm volatile("ldmatrix.sync.aligned.m8n8.x4.shared.b16 {%0,%1,%2,%3}, [%4];"
                 : "=r"(r0), "=r"(r1), "=r"(r2), "=r"(r3) : "r"(addr));
}
__device__ __forceinline__ void mma16816(float* d, const uint32_t* a, uint32_t b0, uint32_t b1) {
    asm volatile("mma.sync.aligned.m16n8k16.row.col.f32.bf16.bf16.f32 "
                 "{%0,%1,%2,%3}, {%4,%5,%6,%7}, {%8,%9}, {%0,%1,%2,%3};"
                 : "+f"(d[0]), "+f"(d[1]), "+f"(d[2]), "+f"(d[3])
                 : "r"(a[0]), "r"(a[1]), "r"(a[2]), "r"(a[3]), "r"(b0), "r"(b1));
}
__device__ __forceinline__ void mma16816h(float* d, const uint32_t* a, uint32_t b0, uint32_t b1) {
    asm volatile("mma.sync.aligned.m16n8k16.row.col.f32.f16.f16.f32 "
                 "{%0,%1,%2,%3}, {%4,%5,%6,%7}, {%8,%9}, {%0,%1,%2,%3};"
                 : "+f"(d[0]), "+f"(d[1]), "+f"(d[2]), "+f"(d[3])
                 : "r"(a[0]), "r"(a[1]), "r"(a[2]), "r"(a[3]), "r"(b0), "r"(b1));
}
#define CP_ASYNC16(dst, src) \
    asm volatile("cp.async.cg.shared.global [%0], [%1], 16;" :: "r"(dst), "l"(src))
#define CP_COMMIT() asm volatile("cp.async.commit_group;")
#define CP_WAIT1()  asm volatile("cp.async.wait_group 1;")

__device__ __forceinline__ uint32_t pack_bf16x2(float a, float b) {
    const __nv_bfloat16 ha = __float2bfloat16(a);
    const __nv_bfloat16 hb = __float2bfloat16(b);
    return (uint32_t)__bfloat16_as_ushort(ha) | ((uint32_t)__bfloat16_as_ushort(hb) << 16);
}

// ======================= split-bf16 NT GEMM via mma.sync ====================
// C[M,N] = A'[M,Kp] @ B'[N,Kp]^T, batched via blockIdx.z (strideA/strideB).
// EPI: 0 = +bias -> outF[m*N+n]
//      1 = relu(+bias) -> split triple (hi,hi,lo) into outH [m, 3N]
//      3 = V scatter  outF[b,h,d,s]  (+bias)
//      4 = scores: p = mask ? 0 : exp(acc*scale) -> fp16 outH; col partials -> csP
//      5 = q split scatter: (hi,hi,lo) into outH[(b,h,s), 3*64]  (+bias)
//      6 = k split scatter: (hi,lo,hi) into outH[(b,h,s), 3*64]  (+bias)
template<int EPI>
__global__ void __launch_bounds__(256, 2)
gemm_mma(const __nv_bfloat16* __restrict__ A, const __nv_bfloat16* __restrict__ Bw,
         int N, int Kp, long strideA, long strideB,
         const float* __restrict__ bias, const uint32_t* __restrict__ mb, float scale,
         float* __restrict__ outF, __nv_bfloat16* __restrict__ outH,
         float* __restrict__ csP)
{
    extern __shared__ char dynsm[];
    __shared__ float cs_sm[128];

    const int z = blockIdx.z;
    A  += (size_t)z * strideA;
    Bw += (size_t)z * strideB;

    const int tid  = threadIdx.x;
    const int wid  = tid >> 5;
    const int lane = tid & 31;
    const int m0   = blockIdx.y * 128;
    const int n0   = blockIdx.x * 128;
    const int wm   = (wid & 1) * 64;
    const int wn   = (wid >> 1) * 32;

    const uint32_t smBase = smem_u32(dynsm);

    float acc[4][4][4];
    #pragma unroll
    for (int i = 0; i < 4; ++i)
        #pragma unroll
        for (int j = 0; j < 4; ++j)
            #pragma unroll
            for (int p = 0; p < 4; ++p) acc[i][j][p] = 0.f;

    const int nk = Kp / 32;

    auto stage = [&](int s, int kt) {
        const int kc = kt * 32;
        const uint32_t base = smBase + s * (2 * STAGE_BYTES);
        #pragma unroll
        for (int i = 0; i < 2; ++i) {
            const int id = tid + i * 256;
            const int r  = id >> 2;
            const int c  = (id & 3) * 8;
            const uint32_t dA = base + (uint32_t)(r * 80 + c * 2);
            const uint32_t dB = dA + STAGE_BYTES;
            CP_ASYNC16(dA, &A [(size_t)(m0 + r) * Kp + kc + c]);
            CP_ASYNC16(dB, &Bw[(size_t)(n0 + r) * Kp + kc + c]);
        }
    };

    stage(0, 0); CP_COMMIT();
    stage(1, 1); CP_COMMIT();

    const int lrow = lane & 15;
    const int lcol = (lane >> 4) * 8;

    for (int kt = 0; kt < nk; ++kt) {
        CP_WAIT1();
        __syncthreads();

        const uint32_t aBase = smBase + (kt % 3) * (2 * STAGE_BYTES);
        const uint32_t bBase = aBase + STAGE_BYTES;

        #pragma unroll
        for (int ks = 0; ks < 32; ks += 16) {
            uint32_t a[4][4];
            #pragma unroll
            for (int mi = 0; mi < 4; ++mi) {
                const uint32_t ad = aBase + (uint32_t)(wm + mi * 16 + lrow) * 80
                                          + (uint32_t)(ks + lcol) * 2;
                ldsm_x4(a[mi][0], a[mi][1], a[mi][2], a[mi][3], ad);
            }
            uint32_t b[2][4];
            #pragma unroll
            for (int bj = 0; bj < 2; ++bj) {
                const uint32_t bd = bBase + (uint32_t)(wn + bj * 16 + lrow) * 80
                                          + (uint32_t)(ks + lcol) * 2;
                ldsm_x4(b[bj][0], b[bj][1], b[bj][2], b[bj][3], bd);
            }
            #pragma unroll
            for (int mi = 0; mi < 4; ++mi)
                #pragma unroll
                for (int nj = 0; nj < 4; ++nj)
                    mma16816(acc[mi][nj], a[mi], b[nj >> 1][nj & 1], b[nj >> 1][(nj & 1) + 2]);
        }

        if (kt + 2 < nk) stage((kt + 2) % 3, kt + 2);
        CP_COMMIT();
    }

    // ---------------- epilogue ----------------
    const int r4 = lane >> 2;
    const int c2 = (lane & 3) * 2;

    float cs[4][2];
    #pragma unroll
    for (int nj = 0; nj < 4; ++nj) { cs[nj][0] = 0.f; cs[nj][1] = 0.f; }

    #pragma unroll
    for (int mi = 0; mi < 4; ++mi) {
        #pragma unroll
        for (int half = 0; half < 2; ++half) {
            const int m = m0 + wm + mi * 16 + r4 + half * 8;
            uint32_t word = 0;
            if (EPI == 4) {
                const int bq = z / Hc;
                word = mb[((size_t)bq * Sc + m) * (Sc / 32) + (size_t)(n0 + wn) / 32];
            }
            #pragma unroll
            for (int nj = 0; nj < 4; ++nj) {
                const int n = n0 + wn + nj * 8 + c2;
                float v0 = acc[mi][nj][half * 2];
                float v1 = acc[mi][nj][half * 2 + 1];
                if (EPI != 4) { v0 += bias[n]; v1 += bias[n + 1]; }
                if (EPI == 0) {
                    *reinterpret_cast<float2*>(&outF[(size_t)m * N + n]) = make_float2(v0, v1);
                } else if (EPI == 1) {
                    const float u0 = fmaxf(v0, 0.f), u1 = fmaxf(v1, 0.f);
                    const __nv_bfloat16 h0 = __float2bfloat16(u0);
                    const __nv_bfloat16 h1 = __float2bfloat16(u1);
                    const uint32_t hw = (uint32_t)__bfloat16_as_ushort(h0) |
                                        ((uint32_t)__bfloat16_as_ushort(h1) << 16);
                    const uint32_t lw = pack_bf16x2(u0 - __bfloat162float(h0),
                                                    u1 - __bfloat162float(h1));
                    const size_t rb = (size_t)m * (3 * N);
                    *reinterpret_cast<uint32_t*>(&outH[rb + n])         = hw;
                    *reinterpret_cast<uint32_t*>(&outH[rb + N + n])     = hw;
                    *reinterpret_cast<uint32_t*>(&outH[rb + 2 * N + n]) = lw;
                } else if (EPI == 3) {
                    const int b = m >> 11, s = m & 2047;
                    const int h = n >> 6,  d = n & 63;
                    outF[(((size_t)b * Hc + h) * DHc + d)     * Sc + s] = v0;
                    outF[(((size_t)b * Hc + h) * DHc + d + 1) * Sc + s] = v1;
                } else if (EPI == 4) {
                    const int bit0 = (word >> (n & 31)) & 1;
                    const int bit1 = (word >> ((n + 1) & 31)) & 1;
                    const float e0 = bit0 ? 0.f : __expf(v0 * scale);
                    const float e1 = bit1 ? 0.f : __expf(v1 * scale);
                    __half2 h2 = __floats2half2_rn(e0, e1);
                    *reinterpret_cast<__half2*>(
                        reinterpret_cast<__half*>(outH) + ((size_t)z * Sc + m) * Sc + n) = h2;
                    cs[nj][0] += e0; cs[nj][1] += e1;
                } else { // EPI 5 / 6
                    const int b = m >> 11, s = m & 2047;
                    const int h = n >> 6,  d = n & 63;
                    const __nv_bfloat16 h0 = __float2bfloat16(v0);
                    const __nv_bfloat16 h1 = __float2bfloat16(v1);
                    const uint32_t hw = (uint32_t)__bfloat16_as_ushort(h0) |
                                        ((uint32_t)__bfloat16_as_ushort(h1) << 16);
                    const uint32_t lw = pack_bf16x2(v0 - __bfloat162float(h0),
                                                    v1 - __bfloat162float(h1));
                    const size_t rb = (((size_t)b * Hc + h) * Sc + s) * (3 * DHc);
                    if (EPI == 5) {
                        *reinterpret_cast<uint32_t*>(&outH[rb + d])           = hw;
                        *reinterpret_cast<uint32_t*>(&outH[rb + DHc + d])     = hw;
                        *reinterpret_cast<uint32_t*>(&outH[rb + 2 * DHc + d]) = lw;
                    } else {
                        *reinterpret_cast<uint32_t*>(&outH[rb + d])           = hw;
                        *reinterpret_cast<uint32_t*>(&outH[rb + DHc + d])     = lw;
                        *reinterpret_cast<uint32_t*>(&outH[rb + 2 * DHc + d]) = hw;
                    }
                }
            }
        }
    }

    if (EPI == 4) {
        // reduce per-column sums: 8 lanes share a column (same lane&3)
        #pragma unroll
        for (int nj = 0; nj < 4; ++nj)
            #pragma unroll
            for (int p = 0; p < 2; ++p) {
                float v = cs[nj][p];
                v += __shfl_xor_sync(0xffffffffu, v, 4);
                v += __shfl_xor_sync(0xffffffffu, v, 8);
                v += __shfl_xor_sync(0xffffffffu, v, 16);
                cs[nj][p] = v;
            }
        if (tid < 128) cs_sm[tid] = 0.f;
        __syncthreads();
        if (r4 == 0) {
            #pragma unroll
            for (int nj = 0; nj < 4; ++nj) {
                atomicAdd(&cs_sm[wn + nj * 8 + c2],     cs[nj][0]);  // exactly 2 adds/addr
                atomicAdd(&cs_sm[wn + nj * 8 + c2 + 1], cs[nj][1]);
            }
        }
        __syncthreads();
        if (tid < 128)
            csP[((size_t)z * 16 + blockIdx.y) * Sc + n0 + tid] = cs_sm[tid];
    }
}

// ======================= attn@V: plain fp16 NT GEMM =========================
// o[b, s, h*64+d] = sum_t p[s,t] * vh[d,t]   (vh already normalized by colsum)
// Tile 128x64, k-chunk 32 t, 3-stage cp.async. 8 warps: 2M x 4N, warp 64x16.
#define AV_A_BYTES (128 * 40 * 2)   // 10240
#define AV_B_BYTES (64 * 40 * 2)    // 5120

__global__ void __launch_bounds__(256, 2)
gemm_av_h(const __half* __restrict__ P, const __half* __restrict__ VH,
          float* __restrict__ out)
{
    __shared__ __half sm[3 * (128 + 64) * 40];

    const int z = blockIdx.z;
    const __half* A  = P  + (size_t)z * Sc * Sc;
    const __half* Bm = VH + (size_t)z * DHc * Sc;

    const int tid  = threadIdx.x;
    const int wid  = tid >> 5;
    const int lane = tid & 31;
    const int m0   = blockIdx.y * 128;
    const int wm   = (wid & 1) * 64;
    const int wn   = (wid >> 1) * 16;

    const uint32_t smBase = smem_u32(sm);

    float acc[4][2][4];
    #pragma unroll
    for (int i = 0; i < 4; ++i)
        #pragma unroll
        for (int j = 0; j < 2; ++j)
            #pragma unroll
            for (int p = 0; p < 4; ++p) acc[i][j][p] = 0.f;

    const int nk = Sc / 32;   // 64

    auto stage = [&](int s, int kt) {
        const int kc = kt * 32;
        const uint32_t base = smBase + s * (AV_A_BYTES + AV_B_BYTES);
        #pragma unroll
        for (int i = 0; i < 3; ++i) {
            const int id = tid + i * 256;          // 0..767
            if (id < 512) {
                const int r = id >> 2, c = (id & 3) * 8;
                CP_ASYNC16(base + (uint32_t)(r * 80 + c * 2),
                           &A[(size_t)(m0 + r) * Sc + kc + c]);
            } else {
                const int id2 = id - 512;
                const int r = id2 >> 2, c = (id2 & 3) * 8;
                CP_ASYNC16(base + AV_A_BYTES + (uint32_t)(r * 80 + c * 2),
                           &Bm[(size_t)r * Sc + kc + c]);
            }
        }
    };

    stage(0, 0); CP_COMMIT();
    stage(1, 1); CP_COMMIT();

    const int lrow = lane & 15;
    const int lcol = (lane >> 4) * 8;

    for (int kt = 0; kt < nk; ++kt) {
        CP_WAIT1();
        __syncthreads();

        const uint32_t aBase = smBase + (kt % 3) * (AV_A_BYTES + AV_B_BYTES);
        const uint32_t bBase = aBase + AV_A_BYTES;

        #pragma unroll
        for (int ks = 0; ks < 32; ks += 16) {
            uint32_t a[4][4];
            #pragma unroll
            for (int mi = 0; mi < 4; ++mi) {
                const uint32_t ad = aBase + (uint32_t)(wm + mi * 16 + lrow) * 80
                                          + (uint32_t)(ks + lcol) * 2;
                ldsm_x4(a[mi][0], a[mi][1], a[mi][2], a[mi][3], ad);
            }
            uint32_t b[4];
            const uint32_t bd = bBase + (uint32_t)(wn + lrow) * 80
                                      + (uint32_t)(ks + lcol) * 2;
            ldsm_x4(b[0], b[1], b[2], b[3], bd);
            #pragma unroll
            for (int mi = 0; mi < 4; ++mi)
                #pragma unroll
                for (int nj = 0; nj < 2; ++nj)
                    mma16816h(acc[mi][nj], a[mi], b[nj], b[nj + 2]);
        }

        if (kt + 2 < nk) stage((kt + 2) % 3, kt + 2);
        CP_COMMIT();
    }

    const int b = z / Hc, h = z % Hc;
    const int r4 = lane >> 2;
    const int c2 = (lane & 3) * 2;
    #pragma unroll
    for (int mi = 0; mi < 4; ++mi) {
        #pragma unroll
        for (int half = 0; half < 2; ++half) {
            const int s = m0 + wm + mi * 16 + r4 + half * 8;
            #pragma unroll
            for (int nj = 0; nj < 2; ++nj) {
                const int d = wn + nj * 8 + c2;
                float2 v = make_float2(acc[mi][nj][half * 2], acc[mi][nj][half * 2 + 1]);
                *reinterpret_cast<float2*>(&out[((size_t)b * Sc + s) * Dc + h * DHc + d]) = v;
            }
        }
    }
}

// ======================= small kernels ======================================
template<int PATB>
__global__ void cvt_split(const float* __restrict__ src, __nv_bfloat16* __restrict__ dst, int K)
{
    const size_t i = (size_t)blockIdx.x * blockDim.x + threadIdx.x;
    const size_t rw = i / K, c = i % K;
    const float v = src[i];
    const __nv_bfloat16 hi = __float2bfloat16(v);
    const __nv_bfloat16 lo = __float2bfloat16(v - __bfloat162float(hi));
    __nv_bfloat16* row = dst + rw * (size_t)(3 * K);
    row[c]         = hi;
    row[K + c]     = PATB ? lo : hi;
    row[2 * K + c] = PATB ? hi : lo;
}

__global__ void maskpack_kernel(const int* __restrict__ mask, uint32_t* __restrict__ mb)
{
    const size_t w = (size_t)blockIdx.x * 256 + threadIdx.x;
    const int4* p = reinterpret_cast<const int4*>(mask + w * 32);
    uint32_t bits = 0;
    #pragma unroll
    for (int i = 0; i < 8; ++i) {
        const int4 v = p[i];
        bits |= (v.x ? 1u : 0u) << (i * 4);
        bits |= (v.y ? 1u : 0u) << (i * 4 + 1);
        bits |= (v.z ? 1u : 0u) << (i * 4 + 2);
        bits |= (v.w ? 1u : 0u) << (i * 4 + 3);
    }
    mb[w] = bits;
}

__global__ void colsum_kernel(const float* __restrict__ csp, float* __restrict__ colsum)
{
    const size_t i = (size_t)blockIdx.x * 256 + threadIdx.x;   // z*Sc + t
    const size_t z = i >> 11;
    const int    t = (int)(i & 2047);
    float s = 0.f;
    #pragma unroll
    for (int my = 0; my < 16; ++my)
        s += csp[(z * 16 + my) * Sc + t];
    colsum[i] = s;
}

__global__ void vh_kernel(const float* __restrict__ vt, const float* __restrict__ colsum,
                          __half* __restrict__ vh)
{
    const size_t i = ((size_t)blockIdx.x * 256 + threadIdx.x) * 2;
    const size_t zd = i >> 11;
    const int    t  = (int)(i & 2047);
    const size_t z  = zd >> 6;
    const float2 v = *reinterpret_cast<const float2*>(&vt[i]);
    const float2 c = *reinterpret_cast<const float2*>(&colsum[z * Sc + t]);
    *reinterpret_cast<__half2*>(&vh[i]) =
        __floats2half2_rn(__fdividef(v.x, c.x), __fdividef(v.y, c.y));
}

// LN + residual. SPLIT=0: fp32 out. SPLIT=1: (hi,hi,lo) bf16 triple out.
template<int SPLIT>
__global__ void ln_residual_kernel(const float* __restrict__ in,
                                   const float* __restrict__ gamma,
                                   const float* __restrict__ beta,
                                   float* __restrict__ out,
                                   __nv_bfloat16* __restrict__ outH)
{
    const size_t row = blockIdx.x;
    const float* xr = in + row * Dc;
    const int tid = threadIdx.x;

    const float v0 = xr[tid], v1 = xr[tid + 256], v2 = xr[tid + 512];

    __shared__ float red[256];
    red[tid] = v0 + v1 + v2;
    __syncthreads();
    #pragma unroll
    for (int o = 128; o > 0; o >>= 1) {
        if (tid < o) red[tid] += red[tid + o];
        __syncthreads();
    }
    const float mu = red[0] * (1.f / Dc);
    __syncthreads();

    const float d0 = v0 - mu, d1 = v1 - mu, d2 = v2 - mu;
    red[tid] = d0 * d0 + d1 * d1 + d2 * d2;
    __syncthreads();
    #pragma unroll
    for (int o = 128; o > 0; o >>= 1) {
        if (tid < o) red[tid] += red[tid + o];
        __syncthreads();
    }
    const float rstd = rsqrtf(red[0] * (1.f / Dc) + 1e-5f);

    const float o0 = d0 * rstd * gamma[tid]       + beta[tid]       + v0;
    const float o1 = d1 * rstd * gamma[tid + 256] + beta[tid + 256] + v1;
    const float o2 = d2 * rstd * gamma[tid + 512] + beta[tid + 512] + v2;

    if (SPLIT == 0) {
        float* orow = out + row * Dc;
        orow[tid] = o0; orow[tid + 256] = o1; orow[tid + 512] = o2;
    } else {
        __nv_bfloat16* orow = outH + row * (size_t)(3 * Dc);
        #pragma unroll
        for (int u = 0; u < 3; ++u) {
            const float v = (u == 0) ? o0 : (u == 1) ? o1 : o2;
            const int  c = tid + u * 256;
            const __nv_bfloat16 hi = __float2bfloat16(v);
            const __nv_bfloat16 lo = __float2bfloat16(v - __bfloat162float(hi));
            orow[c] = hi; orow[Dc + c] = hi; orow[2 * Dc + c] = lo;
        }
    }
}

// ---------------------------------------------------------------------------
extern "C" void kernel_launch(void* const* d_in, const int* in_sizes, int n_in,
                              void* d_out, int out_size)
{
    (void)in_sizes; (void)n_in; (void)out_size;
    const float* x    = (const float*)d_in[0];
    const int*   mask = (const int*)d_in[1];
    const float* Wq = (const float*)d_in[2];
    const float* bq = (const float*)d_in[3];
    const float* Wk = (const float*)d_in[4];
    const float* bk = (const float*)d_in[5];
    const float* Wv = (const float*)d_in[6];
    const float* bv = (const float*)d_in[7];
    const float* gamma = (const float*)d_in[8];
    const float* beta  = (const float*)d_in[9];
    const float* W1 = (const float*)d_in[10];
    const float* b1 = (const float*)d_in[11];
    const float* W2 = (const float*)d_in[12];
    const float* b2 = (const float*)d_in[13];
    float* out = (float*)d_out;

    float *vt, *a, *bb, *csp, *colsum;
    __half *ph, *vh;
    uint32_t *mb;
    cudaGetSymbolAddress((void**)&vt,     g_vt);
    cudaGetSymbolAddress((void**)&a,      g_a);
    cudaGetSymbolAddress((void**)&bb,     g_b);
    cudaGetSymbolAddress((void**)&csp,    g_csp);
    cudaGetSymbolAddress((void**)&colsum, g_colsum);
    cudaGetSymbolAddress((void**)&ph,     g_ph);
    cudaGetSymbolAddress((void**)&vh,     g_vh);
    cudaGetSymbolAddress((void**)&mb,     g_mb);

    __nv_bfloat16 *xhl, *ahl, *hhl, *qs, *ks, *wqhl, *wkhl, *wvhl, *w1hl, *w2hl;
    cudaGetSymbolAddress((void**)&xhl,  g_xhl);
    cudaGetSymbolAddress((void**)&ahl,  g_ahl);
    cudaGetSymbolAddress((void**)&hhl,  g_hhl);
    cudaGetSymbolAddress((void**)&qs,   g_qs);
    cudaGetSymbolAddress((void**)&ks,   g_ks);
    cudaGetSymbolAddress((void**)&wqhl, g_wqhl);
    cudaGetSymbolAddress((void**)&wkhl, g_wkhl);
    cudaGetSymbolAddress((void**)&wvhl, g_wvhl);
    cudaGetSymbolAddress((void**)&w1hl, g_w1hl);
    cudaGetSymbolAddress((void**)&w2hl, g_w2hl);

    cudaFuncSetAttribute(gemm_mma<0>, cudaFuncAttributeMaxDynamicSharedMemorySize, GEMM_SMEM);
    cudaFuncSetAttribute(gemm_mma<1>, cudaFuncAttributeMaxDynamicSharedMemorySize, GEMM_SMEM);
    cudaFuncSetAttribute(gemm_mma<3>, cudaFuncAttributeMaxDynamicSharedMemorySize, GEMM_SMEM);
    cudaFuncSetAttribute(gemm_mma<4>, cudaFuncAttributeMaxDynamicSharedMemorySize, GEMM_SMEM);
    cudaFuncSetAttribute(gemm_mma<5>, cudaFuncAttributeMaxDynamicSharedMemorySize, GEMM_SMEM);
    cudaFuncSetAttribute(gemm_mma<6>, cudaFuncAttributeMaxDynamicSharedMemorySize, GEMM_SMEM);

    const int MS = Bc * Sc;               // 8192
    const float scale = 1.0f / sqrtf((float)Sc);

    // 0) mask bit-pack + split conversions
    maskpack_kernel<<<(Bc * Sc * (Sc / 32)) / 256, 256>>>(mask, mb);
    cvt_split<0><<<(MS * Ec) / 256, 256>>>(x,  xhl,  Ec);
    cvt_split<1><<<(Dc * Ec) / 256, 256>>>(Wq, wqhl, Ec);
    cvt_split<1><<<(Dc * Ec) / 256, 256>>>(Wk, wkhl, Ec);
    cvt_split<1><<<(Dc * Ec) / 256, 256>>>(Wv, wvhl, Ec);
    cvt_split<1><<<(Fc * Dc) / 256, 256>>>(W1, w1hl, Dc);
    cvt_split<1><<<(Dc * Fc) / 256, 256>>>(W2, w2hl, Fc);

    // 1) QKV projections
    {
        dim3 grid(Dc / 128, MS / 128);
        gemm_mma<5><<<grid, 256, GEMM_SMEM>>>(xhl, wqhl, Dc, 3 * Ec, 0, 0, bq, nullptr, 0.f, nullptr, qs, nullptr);
        gemm_mma<6><<<grid, 256, GEMM_SMEM>>>(xhl, wkhl, Dc, 3 * Ec, 0, 0, bk, nullptr, 0.f, nullptr, ks, nullptr);
        gemm_mma<3><<<grid, 256, GEMM_SMEM>>>(xhl, wvhl, Dc, 3 * Ec, 0, 0, bv, nullptr, 0.f, vt, nullptr, nullptr);
    }

    // 2) p = exp(masked scores) fp16 + per-tile column partial sums
    {
        dim3 grid(Sc / 128, Sc / 128, Bc * Hc);
        gemm_mma<4><<<grid, 256, GEMM_SMEM>>>(qs, ks, Sc, 3 * DHc,
                                              (long)Sc * 3 * DHc, (long)Sc * 3 * DHc,
                                              nullptr, mb, scale, nullptr,
                                              (__nv_bfloat16*)ph, csp);
    }

    // 3) column sums + normalized V (fp16)
    colsum_kernel<<<(Bc * Hc * Sc) / 256, 256>>>(csp, colsum);
    vh_kernel<<<(Bc * Hc * DHc * Sc) / 512, 256>>>(vt, colsum, vh);

    // 4) o = p @ vh^T -> concat heads (plain fp16 HMMA)
    {
        dim3 grid(1, Sc / 128, Bc * Hc);
        gemm_av_h<<<grid, 256>>>(ph, vh, a);
    }

    // 5) a = LN(a) + a  -> split bf16 triple
    ln_residual_kernel<1><<<MS, 256>>>(a, gamma, beta, nullptr, ahl);

    // 6) h = relu(a @ W1^T + b1) -> split triple
    {
        dim3 grid(Fc / 128, MS / 128);
        gemm_mma<1><<<grid, 256, GEMM_SMEM>>>(ahl, w1hl, Fc, 3 * Dc, 0, 0, b1, nullptr, 0.f, nullptr, hhl, nullptr);
    }

    // 7) bb = h @ W2^T + b2
    {
        dim3 grid(Dc / 128, MS / 128);
        gemm_mma<0><<<grid, 256, GEMM_SMEM>>>(hhl, w2hl, Dc, 3 * Fc, 0, 0, b2, nullptr, 0.f, bb, nullptr, nullptr);
    }

    // 8) out = LN(bb) + bb
    ln_residual_kernel<0><<<MS, 256>>>(bb, gamma, beta, out, nullptr);
}

// round 10
// speedup vs baseline: 6.1576x; 2.0731x over previous
#include <cuda_runtime.h>
#include <cuda_bf16.h>
#include <cuda_fp16.h>
#include <math.h>
#include <stdint.h>

// Problem dims (fixed by the reference)
#define Bc  4
#define Sc  2048
#define Ec  768
#define Dc  768
#define Hc  12
#define DHc 64
#define Fc  3072

#define LDSH 40                      // fp16 per smem row (80 B pitch)
#define STAGE_BYTES (128 * LDSH * 2) // one matrix, one stage = 10240 B
#define GEMM_SMEM (3 * 2 * STAGE_BYTES)

// ---------------- scratch (device globals: allocation-free) ----------------
__device__ float    g_vt[(size_t)Bc*Hc*DHc*Sc];       // [B,H,dh,S] fp32
__device__ __half   g_ph[(size_t)Bc*Hc*Sc*Sc];        // p = exp(masked score) fp16
__device__ __half   g_vh[(size_t)Bc*Hc*DHc*Sc];       // v / colsum, fp16
__device__ float    g_csp[(size_t)Bc*Hc*16*Sc];       // per-mtile column partial sums
__device__ float    g_colsum[(size_t)Bc*Hc*Sc];
__device__ uint32_t g_mb[(size_t)Bc*Sc*(Sc/32)];      // bit-packed mask
__device__ float    g_a [(size_t)Bc*Sc*Dc];
__device__ float    g_b [(size_t)Bc*Sc*Dc];

// fp16 operand buffers
__device__ __half g_xh [(size_t)Bc*Sc*Ec];
__device__ __half g_ah [(size_t)Bc*Sc*Dc];            // post-LN1 fp16
__device__ __half g_hh [(size_t)Bc*Sc*Fc];            // hidden fp16
__device__ __half g_qh [(size_t)Bc*Hc*Sc*DHc];
__device__ __half g_kh [(size_t)Bc*Hc*Sc*DHc];
__device__ __half g_wqh[(size_t)Dc*Ec];
__device__ __half g_wkh[(size_t)Dc*Ec];
__device__ __half g_wvh[(size_t)Dc*Ec];
__device__ __half g_w1h[(size_t)Fc*Dc];
__device__ __half g_w2h[(size_t)Dc*Fc];

// ======================= warp-MMA helpers ===================================
__device__ __forceinline__ uint32_t smem_u32(const void* p) {
    uint32_t a;
    asm("{ .reg .u64 t; cvta.to.shared.u64 t, %1; cvt.u32.u64 %0, t; }" : "=r"(a) : "l"(p));
    return a;
}
__device__ __forceinline__ void ldsm_x4(uint32_t& r0, uint32_t& r1, uint32_t& r2, uint32_t& r3,
                                        uint32_t addr) {
    asm volatile("ldmatrix.sync.aligned.m8n8.x4.shared.b16 {%0,%1,%2,%3}, [%4];"
                 : "=r"(r0), "=r"(r1), "=r"(r2), "=r"(r3) : "r"(addr));
}
__device__ __forceinline__ void mma16816h(float* d, const uint32_t* a, uint32_t b0, uint32_t b1) {
    asm volatile("mma.sync.aligned.m16n8k16.row.col.f32.f16.f16.f32 "
                 "{%0,%1,%2,%3}, {%4,%5,%6,%7}, {%8,%9}, {%0,%1,%2,%3};"
                 : "+f"(d[0]), "+f"(d[1]), "+f"(d[2]), "+f"(d[3])
                 : "r"(a[0]), "r"(a[1]), "r"(a[2]), "r"(a[3]), "r"(b0), "r"(b1));
}
#define CP_ASYNC16(dst, src) \
    asm volatile("cp.async.cg.shared.global [%0], [%1], 16;" :: "r"(dst), "l"(src))
#define CP_COMMIT() asm volatile("cp.async.commit_group;")
#define CP_WAIT1()  asm volatile("cp.async.wait_group 1;")

// ======================= fp16 NT GEMM via mma.sync ==========================
// C[M,N] = A[M,K] @ B[N,K]^T (fp16 operands, fp32 accumulate), batched via z.
// Tile 128x128x32, 3-stage cp.async, 8 warps (2M x 4N), warp tile 64x32.
// EPI: 0 = +bias -> outF[m*N+n]
//      1 = relu(+bias) -> fp16 outH[m*N+n]
//      3 = V scatter  outF[b,h,d,s]  (+bias)
//      4 = scores: p = mask ? 0 : exp(acc*scale) -> fp16 outH; col partials -> csP
//      5 = q/k scatter: fp16 outH[(b,h,s),64]  (+bias)
template<int EPI>
__global__ void __launch_bounds__(256, 2)
gemm_mma(const __half* __restrict__ A, const __half* __restrict__ Bw,
         int N, int Kp, long strideA, long strideB,
         const float* __restrict__ bias, const uint32_t* __restrict__ mb, float scale,
         float* __restrict__ outF, __half* __restrict__ outH,
         float* __restrict__ csP)
{
    extern __shared__ char dynsm[];
    __shared__ float cs_sm[128];

    const int z = blockIdx.z;
    A  += (size_t)z * strideA;
    Bw += (size_t)z * strideB;

    const int tid  = threadIdx.x;
    const int wid  = tid >> 5;
    const int lane = tid & 31;
    const int m0   = blockIdx.y * 128;
    const int n0   = blockIdx.x * 128;
    const int wm   = (wid & 1) * 64;
    const int wn   = (wid >> 1) * 32;

    const uint32_t smBase = smem_u32(dynsm);

    float acc[4][4][4];
    #pragma unroll
    for (int i = 0; i < 4; ++i)
        #pragma unroll
        for (int j = 0; j < 4; ++j)
            #pragma unroll
            for (int p = 0; p < 4; ++p) acc[i][j][p] = 0.f;

    const int nk = Kp / 32;

    auto stage = [&](int s, int kt) {
        const int kc = kt * 32;
        const uint32_t base = smBase + s * (2 * STAGE_BYTES);
        #pragma unroll
        for (int i = 0; i < 2; ++i) {
            const int id = tid + i * 256;
            const int r  = id >> 2;
            const int c  = (id & 3) * 8;
            const uint32_t dA = base + (uint32_t)(r * 80 + c * 2);
            const uint32_t dB = dA + STAGE_BYTES;
            CP_ASYNC16(dA, &A [(size_t)(m0 + r) * Kp + kc + c]);
            CP_ASYNC16(dB, &Bw[(size_t)(n0 + r) * Kp + kc + c]);
        }
    };

    stage(0, 0); CP_COMMIT();
    stage(1, 1); CP_COMMIT();

    const int lrow = lane & 15;
    const int lcol = (lane >> 4) * 8;

    for (int kt = 0; kt < nk; ++kt) {
        CP_WAIT1();
        __syncthreads();

        const uint32_t aBase = smBase + (kt % 3) * (2 * STAGE_BYTES);
        const uint32_t bBase = aBase + STAGE_BYTES;

        #pragma unroll
        for (int ks = 0; ks < 32; ks += 16) {
            uint32_t a[4][4];
            #pragma unroll
            for (int mi = 0; mi < 4; ++mi) {
                const uint32_t ad = aBase + (uint32_t)(wm + mi * 16 + lrow) * 80
                                          + (uint32_t)(ks + lcol) * 2;
                ldsm_x4(a[mi][0], a[mi][1], a[mi][2], a[mi][3], ad);
            }
            uint32_t b[2][4];
            #pragma unroll
            for (int bj = 0; bj < 2; ++bj) {
                const uint32_t bd = bBase + (uint32_t)(wn + bj * 16 + lrow) * 80
                                          + (uint32_t)(ks + lcol) * 2;
                ldsm_x4(b[bj][0], b[bj][1], b[bj][2], b[bj][3], bd);
            }
            #pragma unroll
            for (int mi = 0; mi < 4; ++mi)
                #pragma unroll
                for (int nj = 0; nj < 4; ++nj)
                    mma16816h(acc[mi][nj], a[mi], b[nj >> 1][nj & 1], b[nj >> 1][(nj & 1) + 2]);
        }

        if (kt + 2 < nk) stage((kt + 2) % 3, kt + 2);
        CP_COMMIT();
    }

    // ---------------- epilogue ----------------
    const int r4 = lane >> 2;
    const int c2 = (lane & 3) * 2;

    float cs[4][2];
    #pragma unroll
    for (int nj = 0; nj < 4; ++nj) { cs[nj][0] = 0.f; cs[nj][1] = 0.f; }

    #pragma unroll
    for (int mi = 0; mi < 4; ++mi) {
        #pragma unroll
        for (int half = 0; half < 2; ++half) {
            const int m = m0 + wm + mi * 16 + r4 + half * 8;
            uint32_t word = 0;
            if (EPI == 4) {
                const int bq = z / Hc;
                word = mb[((size_t)bq * Sc + m) * (Sc / 32) + (size_t)(n0 + wn) / 32];
            }
            #pragma unroll
            for (int nj = 0; nj < 4; ++nj) {
                const int n = n0 + wn + nj * 8 + c2;
                float v0 = acc[mi][nj][half * 2];
                float v1 = acc[mi][nj][half * 2 + 1];
                if (EPI != 4) { v0 += bias[n]; v1 += bias[n + 1]; }
                if (EPI == 0) {
                    *reinterpret_cast<float2*>(&outF[(size_t)m * N + n]) = make_float2(v0, v1);
                } else if (EPI == 1) {
                    *reinterpret_cast<__half2*>(&outH[(size_t)m * N + n]) =
                        __floats2half2_rn(fmaxf(v0, 0.f), fmaxf(v1, 0.f));
                } else if (EPI == 3) {
                    const int b = m >> 11, s = m & 2047;
                    const int h = n >> 6,  d = n & 63;
                    outF[(((size_t)b * Hc + h) * DHc + d)     * Sc + s] = v0;
                    outF[(((size_t)b * Hc + h) * DHc + d + 1) * Sc + s] = v1;
                } else if (EPI == 4) {
                    const int bit0 = (word >> (n & 31)) & 1;
                    const int bit1 = (word >> ((n + 1) & 31)) & 1;
                    const float e0 = bit0 ? 0.f : __expf(v0 * scale);
                    const float e1 = bit1 ? 0.f : __expf(v1 * scale);
                    *reinterpret_cast<__half2*>(&outH[((size_t)z * Sc + m) * Sc + n]) =
                        __floats2half2_rn(e0, e1);
                    cs[nj][0] += e0; cs[nj][1] += e1;
                } else { // EPI 5: q/k scatter
                    const int b = m >> 11, s = m & 2047;
                    const int h = n >> 6,  d = n & 63;
                    *reinterpret_cast<__half2*>(
                        &outH[(((size_t)b * Hc + h) * Sc + s) * DHc + d]) =
                        __floats2half2_rn(v0, v1);
                }
            }
        }
    }

    if (EPI == 4) {
        #pragma unroll
        for (int nj = 0; nj < 4; ++nj)
            #pragma unroll
            for (int p = 0; p < 2; ++p) {
                float v = cs[nj][p];
                v += __shfl_xor_sync(0xffffffffu, v, 4);
                v += __shfl_xor_sync(0xffffffffu, v, 8);
                v += __shfl_xor_sync(0xffffffffu, v, 16);
                cs[nj][p] = v;
            }
        if (tid < 128) cs_sm[tid] = 0.f;
        __syncthreads();
        if (r4 == 0) {
            #pragma unroll
            for (int nj = 0; nj < 4; ++nj) {
                atomicAdd(&cs_sm[wn + nj * 8 + c2],     cs[nj][0]);  // 2 adds/addr: commutative
                atomicAdd(&cs_sm[wn + nj * 8 + c2 + 1], cs[nj][1]);
            }
        }
        __syncthreads();
        if (tid < 128)
            csP[((size_t)z * 16 + blockIdx.y) * Sc + n0 + tid] = cs_sm[tid];
    }
}

// ======================= attn@V: plain fp16 NT GEMM =========================
#define AV_A_BYTES (128 * 40 * 2)   // 10240
#define AV_B_BYTES (64 * 40 * 2)    // 5120

__global__ void __launch_bounds__(256, 2)
gemm_av_h(const __half* __restrict__ P, const __half* __restrict__ VH,
          float* __restrict__ out)
{
    __shared__ __half sm[3 * (128 + 64) * 40];

    const int z = blockIdx.z;
    const __half* A  = P  + (size_t)z * Sc * Sc;
    const __half* Bm = VH + (size_t)z * DHc * Sc;

    const int tid  = threadIdx.x;
    const int wid  = tid >> 5;
    const int lane = tid & 31;
    const int m0   = blockIdx.y * 128;
    const int wm   = (wid & 1) * 64;
    const int wn   = (wid >> 1) * 16;

    const uint32_t smBase = smem_u32(sm);

    float acc[4][2][4];
    #pragma unroll
    for (int i = 0; i < 4; ++i)
        #pragma unroll
        for (int j = 0; j < 2; ++j)
            #pragma unroll
            for (int p = 0; p < 4; ++p) acc[i][j][p] = 0.f;

    const int nk = Sc / 32;   // 64

    auto stage = [&](int s, int kt) {
        const int kc = kt * 32;
        const uint32_t base = smBase + s * (AV_A_BYTES + AV_B_BYTES);
        #pragma unroll
        for (int i = 0; i < 3; ++i) {
            const int id = tid + i * 256;
            if (id < 512) {
                const int r = id >> 2, c = (id & 3) * 8;
                CP_ASYNC16(base + (uint32_t)(r * 80 + c * 2),
                           &A[(size_t)(m0 + r) * Sc + kc + c]);
            } else {
                const int id2 = id - 512;
                const int r = id2 >> 2, c = (id2 & 3) * 8;
                CP_ASYNC16(base + AV_A_BYTES + (uint32_t)(r * 80 + c * 2),
                           &Bm[(size_t)r * Sc + kc + c]);
            }
        }
    };

    stage(0, 0); CP_COMMIT();
    stage(1, 1); CP_COMMIT();

    const int lrow = lane & 15;
    const int lcol = (lane >> 4) * 8;

    for (int kt = 0; kt < nk; ++kt) {
        CP_WAIT1();
        __syncthreads();

        const uint32_t aBase = smBase + (kt % 3) * (AV_A_BYTES + AV_B_BYTES);
        const uint32_t bBase = aBase + AV_A_BYTES;

        #pragma unroll
        for (int ks = 0; ks < 32; ks += 16) {
            uint32_t a[4][4];
            #pragma unroll
            for (int mi = 0; mi < 4; ++mi) {
                const uint32_t ad = aBase + (uint32_t)(wm + mi * 16 + lrow) * 80
                                          + (uint32_t)(ks + lcol) * 2;
                ldsm_x4(a[mi][0], a[mi][1], a[mi][2], a[mi][3], ad);
            }
            uint32_t b[4];
            const uint32_t bd = bBase + (uint32_t)(wn + lrow) * 80
                                      + (uint32_t)(ks + lcol) * 2;
            ldsm_x4(b[0], b[1], b[2], b[3], bd);
            #pragma unroll
            for (int mi = 0; mi < 4; ++mi)
                #pragma unroll
                for (int nj = 0; nj < 2; ++nj)
                    mma16816h(acc[mi][nj], a[mi], b[nj], b[nj + 2]);
        }

        if (kt + 2 < nk) stage((kt + 2) % 3, kt + 2);
        CP_COMMIT();
    }

    const int b = z / Hc, h = z % Hc;
    const int r4 = lane >> 2;
    const int c2 = (lane & 3) * 2;
    #pragma unroll
    for (int mi = 0; mi < 4; ++mi) {
        #pragma unroll
        for (int half = 0; half < 2; ++half) {
            const int s = m0 + wm + mi * 16 + r4 + half * 8;
            #pragma unroll
            for (int nj = 0; nj < 2; ++nj) {
                const int d = wn + nj * 8 + c2;
                float2 v = make_float2(acc[mi][nj][half * 2], acc[mi][nj][half * 2 + 1]);
                *reinterpret_cast<float2*>(&out[((size_t)b * Sc + s) * Dc + h * DHc + d]) = v;
            }
        }
    }
}

// ======================= small kernels ======================================
__global__ void cvt_h(const float* __restrict__ src, __half* __restrict__ dst)
{
    const size_t i = ((size_t)blockIdx.x * 256 + threadIdx.x) * 2;
    const float2 v = *reinterpret_cast<const float2*>(&src[i]);
    *reinterpret_cast<__half2*>(&dst[i]) = __floats2half2_rn(v.x, v.y);
}

__global__ void maskpack_kernel(const int* __restrict__ mask, uint32_t* __restrict__ mb)
{
    const size_t w = (size_t)blockIdx.x * 256 + threadIdx.x;
    const int4* p = reinterpret_cast<const int4*>(mask + w * 32);
    uint32_t bits = 0;
    #pragma unroll
    for (int i = 0; i < 8; ++i) {
        const int4 v = p[i];
        bits |= (v.x ? 1u : 0u) << (i * 4);
        bits |= (v.y ? 1u : 0u) << (i * 4 + 1);
        bits |= (v.z ? 1u : 0u) << (i * 4 + 2);
        bits |= (v.w ? 1u : 0u) << (i * 4 + 3);
    }
    mb[w] = bits;
}

__global__ void colsum_kernel(const float* __restrict__ csp, float* __restrict__ colsum)
{
    const size_t i = (size_t)blockIdx.x * 256 + threadIdx.x;   // z*Sc + t
    const size_t z = i >> 11;
    const int    t = (int)(i & 2047);
    float s = 0.f;
    #pragma unroll
    for (int my = 0; my < 16; ++my)
        s += csp[(z * 16 + my) * Sc + t];
    colsum[i] = s;
}

__global__ void vh_kernel(const float* __restrict__ vt, const float* __restrict__ colsum,
                          __half* __restrict__ vh)
{
    const size_t i = ((size_t)blockIdx.x * 256 + threadIdx.x) * 2;
    const size_t zd = i >> 11;
    const int    t  = (int)(i & 2047);
    const size_t z  = zd >> 6;
    const float2 v = *reinterpret_cast<const float2*>(&vt[i]);
    const float2 c = *reinterpret_cast<const float2*>(&colsum[z * Sc + t]);
    *reinterpret_cast<__half2*>(&vh[i]) =
        __floats2half2_rn(__fdividef(v.x, c.x), __fdividef(v.y, c.y));
}

// LN + residual. HOUT=0: fp32 out. HOUT=1: fp16 out.
template<int HOUT>
__global__ void ln_residual_kernel(const float* __restrict__ in,
                                   const float* __restrict__ gamma,
                                   const float* __restrict__ beta,
                                   float* __restrict__ out,
                                   __half* __restrict__ outH)
{
    const size_t row = blockIdx.x;
    const float* xr = in + row * Dc;
    const int tid = threadIdx.x;

    const float v0 = xr[tid], v1 = xr[tid + 256], v2 = xr[tid + 512];

    __shared__ float red[256];
    red[tid] = v0 + v1 + v2;
    __syncthreads();
    #pragma unroll
    for (int o = 128; o > 0; o >>= 1) {
        if (tid < o) red[tid] += red[tid + o];
        __syncthreads();
    }
    const float mu = red[0] * (1.f / Dc);
    __syncthreads();

    const float d0 = v0 - mu, d1 = v1 - mu, d2 = v2 - mu;
    red[tid] = d0 * d0 + d1 * d1 + d2 * d2;
    __syncthreads();
    #pragma unroll
    for (int o = 128; o > 0; o >>= 1) {
        if (tid < o) red[tid] += red[tid + o];
        __syncthreads();
    }
    const float rstd = rsqrtf(red[0] * (1.f / Dc) + 1e-5f);

    const float o0 = d0 * rstd * gamma[tid]       + beta[tid]       + v0;
    const float o1 = d1 * rstd * gamma[tid + 256] + beta[tid + 256] + v1;
    const float o2 = d2 * rstd * gamma[tid + 512] + beta[tid + 512] + v2;

    if (HOUT == 0) {
        float* orow = out + row * Dc;
        orow[tid] = o0; orow[tid + 256] = o1; orow[tid + 512] = o2;
    } else {
        __half* orow = outH + row * Dc;
        orow[tid]       = __float2half(o0);
        orow[tid + 256] = __float2half(o1);
        orow[tid + 512] = __float2half(o2);
    }
}

// ---------------------------------------------------------------------------
extern "C" void kernel_launch(void* const* d_in, const int* in_sizes, int n_in,
                              void* d_out, int out_size)
{
    (void)in_sizes; (void)n_in; (void)out_size;
    const float* x    = (const float*)d_in[0];
    const int*   mask = (const int*)d_in[1];
    const float* Wq = (const float*)d_in[2];
    const float* bq = (const float*)d_in[3];
    const float* Wk = (const float*)d_in[4];
    const float* bk = (const float*)d_in[5];
    const float* Wv = (const float*)d_in[6];
    const float* bv = (const float*)d_in[7];
    const float* gamma = (const float*)d_in[8];
    const float* beta  = (const float*)d_in[9];
    const float* W1 = (const float*)d_in[10];
    const float* b1 = (const float*)d_in[11];
    const float* W2 = (const float*)d_in[12];
    const float* b2 = (const float*)d_in[13];
    float* out = (float*)d_out;

    float *vt, *a, *bb, *csp, *colsum;
    __half *ph, *vh;
    uint32_t *mb;
    cudaGetSymbolAddress((void**)&vt,     g_vt);
    cudaGetSymbolAddress((void**)&a,      g_a);
    cudaGetSymbolAddress((void**)&bb,     g_b);
    cudaGetSymbolAddress((void**)&csp,    g_csp);
    cudaGetSymbolAddress((void**)&colsum, g_colsum);
    cudaGetSymbolAddress((void**)&ph,     g_ph);
    cudaGetSymbolAddress((void**)&vh,     g_vh);
    cudaGetSymbolAddress((void**)&mb,     g_mb);

    __half *xh, *ah, *hh, *qh, *kh, *wqh, *wkh, *wvh, *w1h, *w2h;
    cudaGetSymbolAddress((void**)&xh,  g_xh);
    cudaGetSymbolAddress((void**)&ah,  g_ah);
    cudaGetSymbolAddress((void**)&hh,  g_hh);
    cudaGetSymbolAddress((void**)&qh,  g_qh);
    cudaGetSymbolAddress((void**)&kh,  g_kh);
    cudaGetSymbolAddress((void**)&wqh, g_wqh);
    cudaGetSymbolAddress((void**)&wkh, g_wkh);
    cudaGetSymbolAddress((void**)&wvh, g_wvh);
    cudaGetSymbolAddress((void**)&w1h, g_w1h);
    cudaGetSymbolAddress((void**)&w2h, g_w2h);

    cudaFuncSetAttribute(gemm_mma<0>, cudaFuncAttributeMaxDynamicSharedMemorySize, GEMM_SMEM);
    cudaFuncSetAttribute(gemm_mma<1>, cudaFuncAttributeMaxDynamicSharedMemorySize, GEMM_SMEM);
    cudaFuncSetAttribute(gemm_mma<3>, cudaFuncAttributeMaxDynamicSharedMemorySize, GEMM_SMEM);
    cudaFuncSetAttribute(gemm_mma<4>, cudaFuncAttributeMaxDynamicSharedMemorySize, GEMM_SMEM);
    cudaFuncSetAttribute(gemm_mma<5>, cudaFuncAttributeMaxDynamicSharedMemorySize, GEMM_SMEM);

    const int MS = Bc * Sc;               // 8192
    const float scale = 1.0f / sqrtf((float)Sc);

    // 0) mask bit-pack + fp16 conversions
    maskpack_kernel<<<(Bc * Sc * (Sc / 32)) / 256, 256>>>(mask, mb);
    cvt_h<<<(MS * Ec) / 512, 256>>>(x,  xh);
    cvt_h<<<(Dc * Ec) / 512, 256>>>(Wq, wqh);
    cvt_h<<<(Dc * Ec) / 512, 256>>>(Wk, wkh);
    cvt_h<<<(Dc * Ec) / 512, 256>>>(Wv, wvh);
    cvt_h<<<(Fc * Dc) / 512, 256>>>(W1, w1h);
    cvt_h<<<(Dc * Fc) / 512, 256>>>(W2, w2h);

    // 1) QKV projections
    {
        dim3 grid(Dc / 128, MS / 128);
        gemm_mma<5><<<grid, 256, GEMM_SMEM>>>(xh, wqh, Dc, Ec, 0, 0, bq, nullptr, 0.f, nullptr, qh, nullptr);
        gemm_mma<5><<<grid, 256, GEMM_SMEM>>>(xh, wkh, Dc, Ec, 0, 0, bk, nullptr, 0.f, nullptr, kh, nullptr);
        gemm_mma<3><<<grid, 256, GEMM_SMEM>>>(xh, wvh, Dc, Ec, 0, 0, bv, nullptr, 0.f, vt, nullptr, nullptr);
    }

    // 2) p = exp(masked scores) fp16 + per-tile column partial sums
    {
        dim3 grid(Sc / 128, Sc / 128, Bc * Hc);
        gemm_mma<4><<<grid, 256, GEMM_SMEM>>>(qh, kh, Sc, DHc,
                                              (long)Sc * DHc, (long)Sc * DHc,
                                              nullptr, mb, scale, nullptr, ph, csp);
    }

    // 3) column sums + normalized V (fp16)
    colsum_kernel<<<(Bc * Hc * Sc) / 256, 256>>>(csp, colsum);
    vh_kernel<<<(Bc * Hc * DHc * Sc) / 512, 256>>>(vt, colsum, vh);

    // 4) o = p @ vh^T -> concat heads
    {
        dim3 grid(1, Sc / 128, Bc * Hc);
        gemm_av_h<<<grid, 256>>>(ph, vh, a);
    }

    // 5) a = LN(a) + a  -> fp16
    ln_residual_kernel<1><<<MS, 256>>>(a, gamma, beta, nullptr, ah);

    // 6) h = relu(a @ W1^T + b1) -> fp16
    {
        dim3 grid(Fc / 128, MS / 128);
        gemm_mma<1><<<grid, 256, GEMM_SMEM>>>(ah, w1h, Fc, Dc, 0, 0, b1, nullptr, 0.f, nullptr, hh, nullptr);
    }

    // 7) bb = h @ W2^T + b2
    {
        dim3 grid(Dc / 128, MS / 128);
        gemm_mma<0><<<grid, 256, GEMM_SMEM>>>(hh, w2h, Dc, Fc, 0, 0, b2, nullptr, 0.f, bb, nullptr, nullptr);
    }

    // 8) out = LN(bb) + bb
    ln_residual_kernel<0><<<MS, 256>>>(bb, gamma, beta, out, nullptr);
}